// round 12
// baseline (speedup 1.0000x reference)
#include <cuda_runtime.h>
#include <cuda_bf16.h>
#include <cuda_fp16.h>
#include <stdint.h>
#include <math.h>

// ---------------- problem constants ----------------
#define BSZ   1024
#define OC    96
#define DW    200          // d_embd
#define HW    400          // 20*20
#define NENT  40000
#define NFC   115200       // 3*96*400
#define EPSB  1e-5f
#define SK1   18
#define CH1   (NFC / SK1)  // 6400
#define NK1   (CH1 / 16)   // 400 k-steps of 16
#define KP2   208          // gemm2 K padded to mult of 16
#define NK2   (KP2 / 16)   // 13

// ---------------- device scratch ----------------
__device__ float g_x[BSZ * HW];
__device__ float g_bn0[2];
__device__ float g_bsum[3 * BSZ * OC];
__device__ float g_chsum[3 * OC];
__device__ float g_chsq[3 * OC];
__device__ float g_alpha[3 * OC];
__device__ float g_beta[3 * OC];
__device__ float g_scale[3 * BSZ * OC];
__device__ __align__(128) __half g_A [(long)BSZ * NFC];   // activations fp16
__device__ __align__(128) __half g_W [(long)DW * NFC];    // fc weight fp16
__device__ float g_c1p[SK1 * BSZ * DW];
__device__ float g_c1[BSZ * DW];
__device__ __align__(128) __half g_z [BSZ * KP2];         // BN2 output fp16
__device__ __align__(128) __half g_n [(long)NENT * KP2];  // n_feats fp16

// ---------------- PTX helpers ----------------
__device__ __forceinline__ void ldsm4(unsigned r[4], unsigned addr) {
    asm volatile("ldmatrix.sync.aligned.m8n8.x4.shared.b16 {%0,%1,%2,%3}, [%4];"
        : "=r"(r[0]), "=r"(r[1]), "=r"(r[2]), "=r"(r[3]) : "r"(addr));
}
__device__ __forceinline__ void mma_fp16(float* c, const unsigned* a,
                                         unsigned b0, unsigned b1) {
    asm volatile(
        "mma.sync.aligned.m16n8k16.row.col.f32.f16.f16.f32 "
        "{%0,%1,%2,%3}, {%4,%5,%6,%7}, {%8,%9}, {%0,%1,%2,%3};"
        : "+f"(c[0]), "+f"(c[1]), "+f"(c[2]), "+f"(c[3])
        : "r"(a[0]), "r"(a[1]), "r"(a[2]), "r"(a[3]), "r"(b0), "r"(b1));
}
__device__ __forceinline__ void cpa16(unsigned s, const void* g) {
    asm volatile("cp.async.ca.shared.global [%0], [%1], 16;" :: "r"(s), "l"(g));
}
__device__ __forceinline__ void cpa16z(unsigned s, const void* g, int srcsz) {
    asm volatile("cp.async.ca.shared.global [%0], [%1], 16, %2;"
                 :: "r"(s), "l"(g), "r"(srcsz));
}

// ---------------- kernel 0: zero atomics ----------------
__global__ void zero_stats() {
    int t = threadIdx.x;
    if (t < 2) g_bn0[t] = 0.f;
    if (t < 3 * OC) { g_chsum[t] = 0.f; g_chsq[t] = 0.f; }
}

// ---------------- kernel 1: gather + chequer + BN0 stats ----------------
__global__ void __launch_bounds__(128) gather_bn0(
    const float* __restrict__ n_feats, const float* __restrict__ r_feats,
    const int* __restrict__ sub, const int* __restrict__ rel)
{
    int b = blockIdx.x, t = threadIdx.x;
    int sb = sub[b], rb = rel[b];
    float s = 0.f, q = 0.f;
    for (int i = t; i < HW; i += 128) {
        float v = (i & 1) ? r_feats[rb * DW + (i >> 1)]
                          : n_feats[sb * DW + (i >> 1)];
        g_x[b * HW + i] = v;
        s += v; q += v * v;
    }
    __shared__ float ss[128], sq[128];
    ss[t] = s; sq[t] = q; __syncthreads();
    for (int st = 64; st > 0; st >>= 1) {
        if (t < st) { ss[t] += ss[t + st]; sq[t] += sq[t + st]; }
        __syncthreads();
    }
    if (t == 0) { atomicAdd(&g_bn0[0], ss[0]); atomicAdd(&g_bn0[1], sq[0]); }
}

// ---------------- conv helpers ----------------
__device__ __forceinline__ float conv_point(
    const float* __restrict__ xs, const float* __restrict__ fo,
    int brch, int h, int w)
{
    float acc = 0.f;
    if (brch == 0) {
        const float* xr = &xs[h * 20];
        acc = xr[w] * fo[2];
        if (w >= 2)  acc += xr[w - 2] * fo[0];
        if (w >= 1)  acc += xr[w - 1] * fo[1];
        if (w <= 18) acc += xr[w + 1] * fo[3];
        if (w <= 17) acc += xr[w + 2] * fo[4];
    } else if (brch == 1) {
        #pragma unroll
        for (int dh = 0; dh < 3; dh++) {
            int hh = h + dh - 1;
            if (hh < 0 || hh >= 20) continue;
            const float* xr = &xs[hh * 20];
            #pragma unroll
            for (int dw = 0; dw < 3; dw++) {
                int ww = w + dw - 1;
                if (ww >= 0 && ww < 20) acc += xr[ww] * fo[dh * 3 + dw];
            }
        }
    } else {
        #pragma unroll
        for (int dh = 0; dh < 5; dh++) {
            int hh = h + dh - 2;
            if (hh >= 0 && hh < 20) acc += xs[hh * 20 + w] * fo[dh];
        }
    }
    return acc;
}

// ---------------- kernel 2a: conv stats pass ----------------
__global__ void __launch_bounds__(384) conv3_stats(
    const float* __restrict__ f1, const float* __restrict__ f2,
    const float* __restrict__ f3, const int* __restrict__ rel,
    const float* __restrict__ bn0g, const float* __restrict__ bn0b)
{
    __shared__ float xs[HW];
    __shared__ float fs[OC * 9];
    int b = blockIdx.x, brch = blockIdx.y, t = threadIdx.x;

    float N0 = (float)BSZ * HW;
    float mean = g_bn0[0] / N0;
    float var  = g_bn0[1] / N0 - mean * mean;
    float a0 = bn0g[0] * rsqrtf(var + EPSB);
    float b0 = bn0b[0] - mean * a0;

    for (int i = t; i < HW; i += 384) xs[i] = g_x[b * HW + i] * a0 + b0;

    int rb = rel[b];
    int flen = (brch == 1) ? OC * 9 : OC * 5;
    int fstr = (brch == 1) ? 9 : 5;
    const float* fp = (brch == 0 ? f1 : (brch == 1 ? f2 : f3)) + (long)rb * flen;
    for (int i = t; i < flen; i += 384) fs[i] = fp[i];
    __syncthreads();

    int oc = t >> 2, q = t & 3;
    const float* fo = &fs[oc * fstr];
    float lsum = 0.f, lsq = 0.f;
    for (int p = q * 100; p < q * 100 + 100; p++) {
        int h = p / 20, w = p - h * 20;
        float acc = conv_point(xs, fo, brch, h, w);
        lsum += acc; lsq += acc * acc;
    }
    lsum += __shfl_down_sync(0xffffffffu, lsum, 2, 4);
    lsum += __shfl_down_sync(0xffffffffu, lsum, 1, 4);
    lsq  += __shfl_down_sync(0xffffffffu, lsq, 2, 4);
    lsq  += __shfl_down_sync(0xffffffffu, lsq, 1, 4);
    if (q == 0) {
        g_bsum[(brch * BSZ + b) * OC + oc] = lsum;
        atomicAdd(&g_chsum[brch * OC + oc], lsum);
        atomicAdd(&g_chsq[brch * OC + oc], lsq);
    }
}

// ---------------- kernel 3: BN affine ----------------
__global__ void bnaff(
    const float* __restrict__ g1, const float* __restrict__ b1,
    const float* __restrict__ g2, const float* __restrict__ b2,
    const float* __restrict__ g3, const float* __restrict__ b3)
{
    int i = threadIdx.x;
    if (i < 3 * OC) {
        int brch = i / OC, c = i - brch * OC;
        float N = (float)BSZ * HW;
        float mean = g_chsum[i] / N;
        float var  = g_chsq[i] / N - mean * mean;
        const float* g = brch == 0 ? g1 : (brch == 1 ? g2 : g3);
        const float* bb = brch == 0 ? b1 : (brch == 1 ? b2 : b3);
        float a = g[c] * rsqrtf(var + EPSB);
        g_alpha[i] = a;
        g_beta[i]  = bb[c] - mean * a;
    }
}

// ---------------- reductions ----------------
__device__ __forceinline__ float redsum128(float v, float* sm) {
    int t = threadIdx.x;
    sm[t] = v; __syncthreads();
    for (int s = 64; s > 0; s >>= 1) {
        if (t < s) sm[t] += sm[t + s];
        __syncthreads();
    }
    float r = sm[0]; __syncthreads();
    return r;
}
__device__ __forceinline__ float redmax128(float v, float* sm) {
    int t = threadIdx.x;
    sm[t] = v; __syncthreads();
    for (int s = 64; s > 0; s >>= 1) {
        if (t < s) sm[t] = fmaxf(sm[t], sm[t + s]);
        __syncthreads();
    }
    float r = sm[0]; __syncthreads();
    return r;
}

// ---------------- kernel 4: SE + ATT gates ----------------
__global__ void __launch_bounds__(128) gates(
    const float* __restrict__ s1w1, const float* __restrict__ s1w2,
    const float* __restrict__ s2w1, const float* __restrict__ s2w2,
    const float* __restrict__ s3w1, const float* __restrict__ s3w2,
    const float* __restrict__ aw1, const float* __restrict__ aw2)
{
    __shared__ float sm[128];
    int b = blockIdx.x, t = threadIdx.x;
    bool act = t < OC;
    int oc = act ? t : 0;

    const float* w1s[3] = {s1w1, s2w1, s3w1};
    const float* w2s[3] = {s1w2, s2w2, s3w2};

    float pool[3], seg[3];
    #pragma unroll
    for (int br = 0; br < 3; br++) {
        float p = fmaf(g_alpha[br * OC + oc],
                       g_bsum[(br * BSZ + b) * OC + oc] * (1.f / HW),
                       g_beta[br * OC + oc]);
        pool[br] = act ? p : 0.f;
    }
    #pragma unroll
    for (int br = 0; br < 3; br++) {
        float h0 = redsum128(act ? pool[br] * w1s[br][oc] : 0.f, sm);
        float h1 = redsum128(act ? pool[br] * w1s[br][OC + oc] : 0.f, sm);
        h0 = fmaxf(h0, 0.f); h1 = fmaxf(h1, 0.f);
        float lg = h0 * w2s[br][oc * 2] + h1 * w2s[br][oc * 2 + 1];
        seg[br] = 1.f / (1.f + expf(-lg));
    }
    float attp = seg[0] * pool[0] + seg[1] * pool[1] + seg[2] * pool[2];
    float a0 = fmaxf(redsum128(act ? attp * aw1[oc] : 0.f, sm), 0.f);
    float a1 = fmaxf(redsum128(act ? attp * aw1[OC + oc] : 0.f, sm), 0.f);

    float l[3], mx = -1e30f;
    #pragma unroll
    for (int br = 0; br < 3; br++) {
        l[br] = act ? (a0 * aw2[(br * OC + oc) * 2] + a1 * aw2[(br * OC + oc) * 2 + 1])
                    : -1e30f;
        mx = fmaxf(mx, l[br]);
    }
    float gm = redmax128(mx, sm);
    float e[3], le = 0.f;
    #pragma unroll
    for (int br = 0; br < 3; br++) { e[br] = expf(l[br] - gm); le += e[br]; }
    float S = redsum128(le, sm);
    if (act) {
        #pragma unroll
        for (int br = 0; br < 3; br++)
            g_scale[(br * BSZ + b) * OC + oc] = seg[br] * e[br] / S;
    }
}

// ---------------- kernel 2b: conv recompute + gate + relu -> fp16 ----------------
__global__ void __launch_bounds__(384) conv3_fused(
    const float* __restrict__ f1, const float* __restrict__ f2,
    const float* __restrict__ f3, const int* __restrict__ rel,
    const float* __restrict__ bn0g, const float* __restrict__ bn0b)
{
    __shared__ float xs[HW];
    __shared__ float fs[OC * 9];
    __shared__ float sA[OC], sBt[OC], sS[OC];
    int b = blockIdx.x, brch = blockIdx.y, t = threadIdx.x;

    float N0 = (float)BSZ * HW;
    float mean = g_bn0[0] / N0;
    float var  = g_bn0[1] / N0 - mean * mean;
    float a0 = bn0g[0] * rsqrtf(var + EPSB);
    float b0 = bn0b[0] - mean * a0;

    for (int i = t; i < HW; i += 384) xs[i] = g_x[b * HW + i] * a0 + b0;

    int rb = rel[b];
    int flen = (brch == 1) ? OC * 9 : OC * 5;
    int fstr = (brch == 1) ? 9 : 5;
    const float* fp = (brch == 0 ? f1 : (brch == 1 ? f2 : f3)) + (long)rb * flen;
    for (int i = t; i < flen; i += 384) fs[i] = fp[i];
    if (t < OC) {
        sA[t]  = g_alpha[brch * OC + t];
        sBt[t] = g_beta[brch * OC + t];
        sS[t]  = g_scale[(brch * BSZ + b) * OC + t];
    }
    __syncthreads();

    long obase = (long)b * NFC + (long)brch * (OC * HW);
    for (int i = t; i < OC * HW; i += 384) {
        int oc = i / HW, p = i - oc * HW;
        int h = p / 20, w = p - h * 20;
        float acc = conv_point(xs, &fs[oc * fstr], brch, h, w);
        float v = fmaxf(fmaf(sA[oc], acc, sBt[oc]) * sS[oc], 0.f);
        g_A[obase + i] = __float2half(v);
    }
}

// ---------------- convert kernels ----------------
__global__ void __launch_bounds__(256) convW(const float* __restrict__ w) {
    long i4 = (long)blockIdx.x * 256 + threadIdx.x;   // 22500 blocks x 4 floats
    float4 v = ((const float4*)w)[i4];
    __half2 hh0, hh1;
    hh0.x = __float2half(v.x); hh0.y = __float2half(v.y);
    hh1.x = __float2half(v.z); hh1.y = __float2half(v.w);
    ((__half2*)g_W)[i4 * 2]     = hh0;
    ((__half2*)g_W)[i4 * 2 + 1] = hh1;
}

__global__ void __launch_bounds__(256) convN(const float* __restrict__ nf) {
    long t = (long)blockIdx.x * 256 + threadIdx.x;   // 32500 blocks: 40000*208
    int e = (int)(t / KP2), j = (int)(t - (long)e * KP2);
    float v = (j < DW) ? nf[(long)e * DW + j] : 0.f;
    g_n[t] = __float2half(v);
}

// ---------------- HMMA fp16 GEMM: 128x128 tile, kstep16, 3 stages, occ-2 --------
// 2 planes (A, B); smem stage = 8KB, 3 stages = 24KB.
// Per-warp jmax: skip B-fragments (and their MMAs) fully beyond Nn.
__device__ __forceinline__ void gemm_hmma(
    const __half* __restrict__ A, long lda,
    const __half* __restrict__ B, long ldb,
    float* __restrict__ C, long ldc, int Nn,
    int m0, int n0, long k0, int nk, const float* __restrict__ bias)
{
    __shared__ __align__(16) char smem[24576];
    unsigned sb = (unsigned)__cvta_generic_to_shared(smem);
    int tid = threadIdx.x, lane = tid & 31, wid = tid >> 5;
    int wm = (wid >> 2) * 64, wn = (wid & 3) * 32;

    // number of valid 16-col B fragments for this warp (0, 1, or 2)
    int rem = Nn - n0 - wn;
    int jmax = (rem > 16) ? 2 : (rem > 0 ? 1 : 0);

    float acc[4][4][4];
    #pragma unroll
    for (int i = 0; i < 4; i++)
        #pragma unroll
        for (int j = 0; j < 4; j++)
            #pragma unroll
            for (int k = 0; k < 4; k++) acc[i][j][k] = 0.f;

    auto issue = [&](int stg_, int kb_) {
        unsigned s0_ = sb + (unsigned)stg_ * 8192u;
        long kk_ = k0 + (long)kb_ * 16;
        #pragma unroll
        for (int ii = 0; ii < 2; ii++) {
            int i_ = tid + ii * 256;
            int pl_ = i_ >> 8, r_ = (i_ >> 1) & 127, c_ = i_ & 1;
            unsigned sw_ = s0_ + (unsigned)pl_ * 4096u + (unsigned)r_ * 32u
                         + (unsigned)((c_ ^ ((r_ >> 2) & 1)) * 16);
            if (pl_ == 0) {
                cpa16(sw_, A + (long)(m0 + r_) * lda + kk_ + c_ * 8);
            } else {
                int ok_ = ((n0 + r_) < Nn) ? 16 : 0;
                cpa16z(sw_, B + (long)(n0 + r_) * ldb + kk_ + c_ * 8, ok_);
            }
        }
        asm volatile("cp.async.commit_group;" ::: "memory");
    };

    // per-warp ldmatrix offsets (stage-invariant)
    int cbit = lane >> 4;
    unsigned aoff[4], boff[2];
    #pragma unroll
    for (int mt = 0; mt < 4; mt++) {
        int r = wm + mt * 16 + (lane & 15);
        aoff[mt] = (unsigned)r * 32u + (unsigned)((cbit ^ ((r >> 2) & 1)) * 16);
    }
    #pragma unroll
    for (int j = 0; j < 2; j++) {
        int r = wn + j * 16 + (lane & 15);
        boff[j] = 4096u + (unsigned)r * 32u
                + (unsigned)((cbit ^ ((r >> 2) & 1)) * 16);
    }

    issue(0, 0);
    issue(1, 1);

    for (int kb = 0; kb < nk; kb++) {
        int st = kb % 3;
        if (kb + 1 < nk)
            asm volatile("cp.async.wait_group 1;" ::: "memory");
        else
            asm volatile("cp.async.wait_group 0;" ::: "memory");
        __syncthreads();
        if (kb + 2 < nk) issue((kb + 2) % 3, kb + 2);   // prefetch early

        unsigned s0 = sb + (unsigned)st * 8192u;
        unsigned bh[2][4];
        #pragma unroll
        for (int j = 0; j < 2; j++)
            if (j < jmax) ldsm4(bh[j], s0 + boff[j]);
        #pragma unroll
        for (int mt = 0; mt < 4; mt++) {
            unsigned ah[4];
            ldsm4(ah, s0 + aoff[mt]);
            #pragma unroll
            for (int j = 0; j < 2; j++) {
                if (j < jmax) {
                    mma_fp16(acc[mt][2*j],   ah, bh[j][0], bh[j][2]);
                    mma_fp16(acc[mt][2*j+1], ah, bh[j][1], bh[j][3]);
                }
            }
        }
        __syncthreads();
    }

    #pragma unroll
    for (int mt = 0; mt < 4; mt++) {
        #pragma unroll
        for (int nt = 0; nt < 4; nt++) {
            int rr = m0 + wm + mt * 16 + (lane >> 2);
            int cc = n0 + wn + nt * 8 + (lane & 3) * 2;
            if (cc < Nn) {
                float bv0 = bias ? bias[cc] : 0.f;
                float bv1 = bias ? bias[cc + 1] : 0.f;
                C[(long)rr * ldc + cc]           = acc[mt][nt][0] + bv0;
                C[(long)rr * ldc + cc + 1]       = acc[mt][nt][1] + bv1;
                C[(long)(rr + 8) * ldc + cc]     = acc[mt][nt][2] + bv0;
                C[(long)(rr + 8) * ldc + cc + 1] = acc[mt][nt][3] + bv1;
            }
        }
    }
}

__global__ void __launch_bounds__(256, 2) gemm1_k() {
    gemm_hmma(g_A, NFC, g_W, NFC,
              g_c1p + (long)blockIdx.z * (BSZ * DW), DW, DW,
              blockIdx.y * 128, blockIdx.x * 128,
              (long)blockIdx.z * CH1, NK1, nullptr);
}

__global__ void __launch_bounds__(256, 2) gemm2_k(
    const float* __restrict__ biasb, float* __restrict__ out) {
    gemm_hmma(g_z, KP2, g_n, KP2,
              out, NENT, NENT,
              blockIdx.y * 128, blockIdx.x * 128, 0, NK2, biasb);
}

// ---------------- kernel 6: split-K reduce (fc bias cancels in BN1d) ----------
__global__ void __launch_bounds__(256) reduce_c1() {
    int idx = blockIdx.x * 256 + threadIdx.x;     // 800*256 == 204800
    float s = 0.f;
    #pragma unroll
    for (int z = 0; z < SK1; z++) s += g_c1p[z * (BSZ * DW) + idx];
    g_c1[idx] = s;
}

// ---------------- kernel 7: BN1d + ReLU -> fp16 (padded to KP2) ----------------
__global__ void __launch_bounds__(256) bn2_relu(
    const float* __restrict__ g2, const float* __restrict__ b2) {
    int d = blockIdx.x, t = threadIdx.x;          // d in [0,KP2)
    if (d >= DW) {
        for (int b = t; b < BSZ; b += 256) g_z[b * KP2 + d] = __float2half(0.f);
        return;
    }
    float s = 0.f, q = 0.f;
    for (int b = t; b < BSZ; b += 256) {
        float v = g_c1[b * DW + d];
        s += v; q += v * v;
    }
    __shared__ float ss[256], sq[256];
    ss[t] = s; sq[t] = q; __syncthreads();
    for (int st = 128; st > 0; st >>= 1) {
        if (t < st) { ss[t] += ss[t + st]; sq[t] += sq[t + st]; }
        __syncthreads();
    }
    float mean = ss[0] / BSZ;
    float var  = sq[0] / BSZ - mean * mean;
    float a = g2[d] * rsqrtf(var + EPSB);
    float bb = b2[d] - mean * a;
    for (int b = t; b < BSZ; b += 256) {
        float v = fmaxf(fmaf(a, g_c1[b * DW + d], bb), 0.f);
        g_z[b * KP2 + d] = __float2half(v);
    }
}

// ---------------- launch ----------------
extern "C" void kernel_launch(void* const* d_in, const int* in_sizes, int n_in,
                              void* d_out, int out_size) {
    const float* n_feats = (const float*)d_in[0];
    const float* r_feats = (const float*)d_in[1];
    const float* filt1   = (const float*)d_in[2];
    const float* filt2   = (const float*)d_in[3];
    const float* filt3   = (const float*)d_in[4];
    const float* bn0_g   = (const float*)d_in[5];
    const float* bn0_b   = (const float*)d_in[6];
    const float* bn1_g   = (const float*)d_in[7];
    const float* bn1_b   = (const float*)d_in[8];
    const float* bn2c_g  = (const float*)d_in[9];
    const float* bn2c_b  = (const float*)d_in[10];
    const float* bn3c_g  = (const float*)d_in[11];
    const float* bn3c_b  = (const float*)d_in[12];
    const float* se1_w1  = (const float*)d_in[13];
    const float* se1_w2  = (const float*)d_in[14];
    const float* se2_w1  = (const float*)d_in[15];
    const float* se2_w2  = (const float*)d_in[16];
    const float* se3_w1  = (const float*)d_in[17];
    const float* se3_w2  = (const float*)d_in[18];
    const float* att_w1  = (const float*)d_in[19];
    const float* att_w2  = (const float*)d_in[20];
    const float* fc_w    = (const float*)d_in[21];
    const float* bn2_g   = (const float*)d_in[23];
    const float* bn2_b   = (const float*)d_in[24];
    const float* bias_b  = (const float*)d_in[25];
    const int*   sub     = (const int*)d_in[26];
    const int*   rel     = (const int*)d_in[27];

    zero_stats<<<1, 3 * OC>>>();
    convW<<<22500, 256>>>(fc_w);
    convN<<<32500, 256>>>(n_feats);
    gather_bn0<<<BSZ, 128>>>(n_feats, r_feats, sub, rel);
    conv3_stats<<<dim3(BSZ, 3), 384>>>(filt1, filt2, filt3, rel, bn0_g, bn0_b);
    bnaff<<<1, 3 * OC>>>(bn1_g, bn1_b, bn2c_g, bn2c_b, bn3c_g, bn3c_b);
    gates<<<BSZ, 128>>>(se1_w1, se1_w2, se2_w1, se2_w2, se3_w1, se3_w2,
                        att_w1, att_w2);
    conv3_fused<<<dim3(BSZ, 3), 384>>>(filt1, filt2, filt3, rel, bn0_g, bn0_b);
    gemm1_k<<<dim3(2, BSZ / 128, SK1), 256>>>();
    reduce_c1<<<800, 256>>>();
    bn2_relu<<<KP2, 256>>>(bn2_g, bn2_b);
    gemm2_k<<<dim3((NENT + 127) / 128, BSZ / 128), 256>>>(bias_b, (float*)d_out);
}

// round 13
// speedup vs baseline: 1.0189x; 1.0189x over previous
#include <cuda_runtime.h>
#include <cuda_bf16.h>
#include <cuda_fp16.h>
#include <stdint.h>
#include <math.h>

// ---------------- problem constants ----------------
#define BSZ   1024
#define OC    96
#define DW    200          // d_embd
#define HW    400          // 20*20
#define NENT  40000
#define NFC   115200       // 3*96*400
#define EPSB  1e-5f
#define SK1   18
#define CH1   (NFC / SK1)  // 6400
#define NK1   (CH1 / 32)   // 200 k-blocks of 32
#define KP2   224          // gemm2 K padded to mult of 32
#define NK2   (KP2 / 32)   // 7

// ---------------- device scratch ----------------
__device__ float g_x[BSZ * HW];
__device__ float g_bn0[2];
__device__ float g_bsum[3 * BSZ * OC];
__device__ float g_chsum[3 * OC];
__device__ float g_chsq[3 * OC];
__device__ float g_alpha[3 * OC];
__device__ float g_beta[3 * OC];
__device__ float g_scale[3 * BSZ * OC];
__device__ __align__(128) __half g_A [(long)BSZ * NFC];   // activations fp16
__device__ __align__(128) __half g_W [(long)DW * NFC];    // fc weight fp16
__device__ float g_c1p[SK1 * BSZ * DW];
__device__ float g_c1[BSZ * DW];
__device__ __align__(128) __half g_z [BSZ * KP2];         // BN2 output fp16
__device__ __align__(128) __half g_n [(long)NENT * KP2];  // n_feats fp16

// ---------------- PTX helpers ----------------
__device__ __forceinline__ void ldsm4(unsigned r[4], unsigned addr) {
    asm volatile("ldmatrix.sync.aligned.m8n8.x4.shared.b16 {%0,%1,%2,%3}, [%4];"
        : "=r"(r[0]), "=r"(r[1]), "=r"(r[2]), "=r"(r[3]) : "r"(addr));
}
__device__ __forceinline__ void mma_fp16(float* c, const unsigned* a,
                                         unsigned b0, unsigned b1) {
    asm volatile(
        "mma.sync.aligned.m16n8k16.row.col.f32.f16.f16.f32 "
        "{%0,%1,%2,%3}, {%4,%5,%6,%7}, {%8,%9}, {%0,%1,%2,%3};"
        : "+f"(c[0]), "+f"(c[1]), "+f"(c[2]), "+f"(c[3])
        : "r"(a[0]), "r"(a[1]), "r"(a[2]), "r"(a[3]), "r"(b0), "r"(b1));
}
__device__ __forceinline__ void cpa16(unsigned s, const void* g) {
    asm volatile("cp.async.ca.shared.global [%0], [%1], 16;" :: "r"(s), "l"(g));
}
__device__ __forceinline__ void cpa16z(unsigned s, const void* g, int srcsz) {
    asm volatile("cp.async.ca.shared.global [%0], [%1], 16, %2;"
                 :: "r"(s), "l"(g), "r"(srcsz));
}

// ---------------- kernel 0: zero atomics ----------------
__global__ void zero_stats() {
    int t = threadIdx.x;
    if (t < 2) g_bn0[t] = 0.f;
    if (t < 3 * OC) { g_chsum[t] = 0.f; g_chsq[t] = 0.f; }
}

// ---------------- kernel 1: gather + chequer + BN0 stats ----------------
__global__ void __launch_bounds__(128) gather_bn0(
    const float* __restrict__ n_feats, const float* __restrict__ r_feats,
    const int* __restrict__ sub, const int* __restrict__ rel)
{
    int b = blockIdx.x, t = threadIdx.x;
    int sb = sub[b], rb = rel[b];
    float s = 0.f, q = 0.f;
    for (int i = t; i < HW; i += 128) {
        float v = (i & 1) ? r_feats[rb * DW + (i >> 1)]
                          : n_feats[sb * DW + (i >> 1)];
        g_x[b * HW + i] = v;
        s += v; q += v * v;
    }
    __shared__ float ss[128], sq[128];
    ss[t] = s; sq[t] = q; __syncthreads();
    for (int st = 64; st > 0; st >>= 1) {
        if (t < st) { ss[t] += ss[t + st]; sq[t] += sq[t + st]; }
        __syncthreads();
    }
    if (t == 0) { atomicAdd(&g_bn0[0], ss[0]); atomicAdd(&g_bn0[1], sq[0]); }
}

// ---------------- conv helpers ----------------
__device__ __forceinline__ float conv_point(
    const float* __restrict__ xs, const float* __restrict__ fo,
    int brch, int h, int w)
{
    float acc = 0.f;
    if (brch == 0) {
        const float* xr = &xs[h * 20];
        acc = xr[w] * fo[2];
        if (w >= 2)  acc += xr[w - 2] * fo[0];
        if (w >= 1)  acc += xr[w - 1] * fo[1];
        if (w <= 18) acc += xr[w + 1] * fo[3];
        if (w <= 17) acc += xr[w + 2] * fo[4];
    } else if (brch == 1) {
        #pragma unroll
        for (int dh = 0; dh < 3; dh++) {
            int hh = h + dh - 1;
            if (hh < 0 || hh >= 20) continue;
            const float* xr = &xs[hh * 20];
            #pragma unroll
            for (int dw = 0; dw < 3; dw++) {
                int ww = w + dw - 1;
                if (ww >= 0 && ww < 20) acc += xr[ww] * fo[dh * 3 + dw];
            }
        }
    } else {
        #pragma unroll
        for (int dh = 0; dh < 5; dh++) {
            int hh = h + dh - 2;
            if (hh >= 0 && hh < 20) acc += xs[hh * 20 + w] * fo[dh];
        }
    }
    return acc;
}

// ---------------- kernel 2a: conv stats pass ----------------
__global__ void __launch_bounds__(384) conv3_stats(
    const float* __restrict__ f1, const float* __restrict__ f2,
    const float* __restrict__ f3, const int* __restrict__ rel,
    const float* __restrict__ bn0g, const float* __restrict__ bn0b)
{
    __shared__ float xs[HW];
    __shared__ float fs[OC * 9];
    int b = blockIdx.x, brch = blockIdx.y, t = threadIdx.x;

    float N0 = (float)BSZ * HW;
    float mean = g_bn0[0] / N0;
    float var  = g_bn0[1] / N0 - mean * mean;
    float a0 = bn0g[0] * rsqrtf(var + EPSB);
    float b0 = bn0b[0] - mean * a0;

    for (int i = t; i < HW; i += 384) xs[i] = g_x[b * HW + i] * a0 + b0;

    int rb = rel[b];
    int flen = (brch == 1) ? OC * 9 : OC * 5;
    int fstr = (brch == 1) ? 9 : 5;
    const float* fp = (brch == 0 ? f1 : (brch == 1 ? f2 : f3)) + (long)rb * flen;
    for (int i = t; i < flen; i += 384) fs[i] = fp[i];
    __syncthreads();

    int oc = t >> 2, q = t & 3;
    const float* fo = &fs[oc * fstr];
    float lsum = 0.f, lsq = 0.f;
    for (int p = q * 100; p < q * 100 + 100; p++) {
        int h = p / 20, w = p - h * 20;
        float acc = conv_point(xs, fo, brch, h, w);
        lsum += acc; lsq += acc * acc;
    }
    lsum += __shfl_down_sync(0xffffffffu, lsum, 2, 4);
    lsum += __shfl_down_sync(0xffffffffu, lsum, 1, 4);
    lsq  += __shfl_down_sync(0xffffffffu, lsq, 2, 4);
    lsq  += __shfl_down_sync(0xffffffffu, lsq, 1, 4);
    if (q == 0) {
        g_bsum[(brch * BSZ + b) * OC + oc] = lsum;
        atomicAdd(&g_chsum[brch * OC + oc], lsum);
        atomicAdd(&g_chsq[brch * OC + oc], lsq);
    }
}

// ---------------- kernel 3: BN affine ----------------
__global__ void bnaff(
    const float* __restrict__ g1, const float* __restrict__ b1,
    const float* __restrict__ g2, const float* __restrict__ b2,
    const float* __restrict__ g3, const float* __restrict__ b3)
{
    int i = threadIdx.x;
    if (i < 3 * OC) {
        int brch = i / OC, c = i - brch * OC;
        float N = (float)BSZ * HW;
        float mean = g_chsum[i] / N;
        float var  = g_chsq[i] / N - mean * mean;
        const float* g = brch == 0 ? g1 : (brch == 1 ? g2 : g3);
        const float* bb = brch == 0 ? b1 : (brch == 1 ? b2 : b3);
        float a = g[c] * rsqrtf(var + EPSB);
        g_alpha[i] = a;
        g_beta[i]  = bb[c] - mean * a;
    }
}

// ---------------- reductions ----------------
__device__ __forceinline__ float redsum128(float v, float* sm) {
    int t = threadIdx.x;
    sm[t] = v; __syncthreads();
    for (int s = 64; s > 0; s >>= 1) {
        if (t < s) sm[t] += sm[t + s];
        __syncthreads();
    }
    float r = sm[0]; __syncthreads();
    return r;
}
__device__ __forceinline__ float redmax128(float v, float* sm) {
    int t = threadIdx.x;
    sm[t] = v; __syncthreads();
    for (int s = 64; s > 0; s >>= 1) {
        if (t < s) sm[t] = fmaxf(sm[t], sm[t + s]);
        __syncthreads();
    }
    float r = sm[0]; __syncthreads();
    return r;
}

// ---------------- kernel 4: SE + ATT gates ----------------
__global__ void __launch_bounds__(128) gates(
    const float* __restrict__ s1w1, const float* __restrict__ s1w2,
    const float* __restrict__ s2w1, const float* __restrict__ s2w2,
    const float* __restrict__ s3w1, const float* __restrict__ s3w2,
    const float* __restrict__ aw1, const float* __restrict__ aw2)
{
    __shared__ float sm[128];
    int b = blockIdx.x, t = threadIdx.x;
    bool act = t < OC;
    int oc = act ? t : 0;

    const float* w1s[3] = {s1w1, s2w1, s3w1};
    const float* w2s[3] = {s1w2, s2w2, s3w2};

    float pool[3], seg[3];
    #pragma unroll
    for (int br = 0; br < 3; br++) {
        float p = fmaf(g_alpha[br * OC + oc],
                       g_bsum[(br * BSZ + b) * OC + oc] * (1.f / HW),
                       g_beta[br * OC + oc]);
        pool[br] = act ? p : 0.f;
    }
    #pragma unroll
    for (int br = 0; br < 3; br++) {
        float h0 = redsum128(act ? pool[br] * w1s[br][oc] : 0.f, sm);
        float h1 = redsum128(act ? pool[br] * w1s[br][OC + oc] : 0.f, sm);
        h0 = fmaxf(h0, 0.f); h1 = fmaxf(h1, 0.f);
        float lg = h0 * w2s[br][oc * 2] + h1 * w2s[br][oc * 2 + 1];
        seg[br] = 1.f / (1.f + expf(-lg));
    }
    float attp = seg[0] * pool[0] + seg[1] * pool[1] + seg[2] * pool[2];
    float a0 = fmaxf(redsum128(act ? attp * aw1[oc] : 0.f, sm), 0.f);
    float a1 = fmaxf(redsum128(act ? attp * aw1[OC + oc] : 0.f, sm), 0.f);

    float l[3], mx = -1e30f;
    #pragma unroll
    for (int br = 0; br < 3; br++) {
        l[br] = act ? (a0 * aw2[(br * OC + oc) * 2] + a1 * aw2[(br * OC + oc) * 2 + 1])
                    : -1e30f;
        mx = fmaxf(mx, l[br]);
    }
    float gm = redmax128(mx, sm);
    float e[3], le = 0.f;
    #pragma unroll
    for (int br = 0; br < 3; br++) { e[br] = expf(l[br] - gm); le += e[br]; }
    float S = redsum128(le, sm);
    if (act) {
        #pragma unroll
        for (int br = 0; br < 3; br++)
            g_scale[(br * BSZ + b) * OC + oc] = seg[br] * e[br] / S;
    }
}

// ---------------- kernel 2b: conv recompute + gate + relu -> fp16 ----------------
__global__ void __launch_bounds__(384) conv3_fused(
    const float* __restrict__ f1, const float* __restrict__ f2,
    const float* __restrict__ f3, const int* __restrict__ rel,
    const float* __restrict__ bn0g, const float* __restrict__ bn0b)
{
    __shared__ float xs[HW];
    __shared__ float fs[OC * 9];
    __shared__ float sA[OC], sBt[OC], sS[OC];
    int b = blockIdx.x, brch = blockIdx.y, t = threadIdx.x;

    float N0 = (float)BSZ * HW;
    float mean = g_bn0[0] / N0;
    float var  = g_bn0[1] / N0 - mean * mean;
    float a0 = bn0g[0] * rsqrtf(var + EPSB);
    float b0 = bn0b[0] - mean * a0;

    for (int i = t; i < HW; i += 384) xs[i] = g_x[b * HW + i] * a0 + b0;

    int rb = rel[b];
    int flen = (brch == 1) ? OC * 9 : OC * 5;
    int fstr = (brch == 1) ? 9 : 5;
    const float* fp = (brch == 0 ? f1 : (brch == 1 ? f2 : f3)) + (long)rb * flen;
    for (int i = t; i < flen; i += 384) fs[i] = fp[i];
    if (t < OC) {
        sA[t]  = g_alpha[brch * OC + t];
        sBt[t] = g_beta[brch * OC + t];
        sS[t]  = g_scale[(brch * BSZ + b) * OC + t];
    }
    __syncthreads();

    long obase = (long)b * NFC + (long)brch * (OC * HW);
    for (int i = t; i < OC * HW; i += 384) {
        int oc = i / HW, p = i - oc * HW;
        int h = p / 20, w = p - h * 20;
        float acc = conv_point(xs, &fs[oc * fstr], brch, h, w);
        float v = fmaxf(fmaf(sA[oc], acc, sBt[oc]) * sS[oc], 0.f);
        g_A[obase + i] = __float2half(v);
    }
}

// ---------------- convert kernels ----------------
__global__ void __launch_bounds__(256) convW(const float* __restrict__ w) {
    long i4 = (long)blockIdx.x * 256 + threadIdx.x;   // 22500 blocks x 4 floats
    float4 v = ((const float4*)w)[i4];
    __half2 hh0, hh1;
    hh0.x = __float2half(v.x); hh0.y = __float2half(v.y);
    hh1.x = __float2half(v.z); hh1.y = __float2half(v.w);
    ((__half2*)g_W)[i4 * 2]     = hh0;
    ((__half2*)g_W)[i4 * 2 + 1] = hh1;
}

__global__ void __launch_bounds__(256) convN(const float* __restrict__ nf) {
    long t = (long)blockIdx.x * 256 + threadIdx.x;   // 35000 blocks: 40000*224
    int e = (int)(t / KP2), j = (int)(t - (long)e * KP2);
    float v = (j < DW) ? nf[(long)e * DW + j] : 0.f;
    g_n[t] = __float2half(v);
}

// ---------------- HMMA fp16 GEMM: 128x128 tile, kstep32, 3 stages, occ-2 --------
// stage (16KB) = sub0[A 4K][B 4K] + sub1[A 4K][B 4K]
__device__ __forceinline__ void gemm_hmma(
    const __half* __restrict__ A, long lda,
    const __half* __restrict__ B, long ldb,
    float* __restrict__ C, long ldc, int Nn,
    int m0, int n0, long k0, int nk, const float* __restrict__ bias)
{
    __shared__ __align__(16) char smem[49152];
    unsigned sb = (unsigned)__cvta_generic_to_shared(smem);
    int tid = threadIdx.x, lane = tid & 31, wid = tid >> 5;
    int wm = (wid >> 2) * 64, wn = (wid & 3) * 32;

    float acc[4][4][4];
    #pragma unroll
    for (int i = 0; i < 4; i++)
        #pragma unroll
        for (int j = 0; j < 4; j++)
            #pragma unroll
            for (int k = 0; k < 4; k++) acc[i][j][k] = 0.f;

    // 1024 chunks of 16B per stage; 4 per thread
    auto issue = [&](int stg_, int kb_) {
        unsigned s0_ = sb + (unsigned)stg_ * 16384u;
        long kk_ = k0 + (long)kb_ * 32;
        #pragma unroll
        for (int ii = 0; ii < 4; ii++) {
            int i_ = tid + ii * 256;
            int sub_ = i_ >> 9, rem_ = i_ & 511;
            int pl_ = rem_ >> 8, r_ = (rem_ >> 1) & 127, c_ = rem_ & 1;
            unsigned sw_ = s0_ + (unsigned)sub_ * 8192u + (unsigned)pl_ * 4096u
                         + (unsigned)r_ * 32u
                         + (unsigned)((c_ ^ ((r_ >> 2) & 1)) * 16);
            long gk_ = kk_ + sub_ * 16 + c_ * 8;
            if (pl_ == 0) {
                cpa16(sw_, A + (long)(m0 + r_) * lda + gk_);
            } else {
                int ok_ = ((n0 + r_) < Nn) ? 16 : 0;
                cpa16z(sw_, B + (long)(n0 + r_) * ldb + gk_, ok_);
            }
        }
        asm volatile("cp.async.commit_group;" ::: "memory");
    };

    // per-warp ldmatrix offsets relative to sub-block base
    int cbit = lane >> 4;
    unsigned aoff[4], boff[2];
    #pragma unroll
    for (int mt = 0; mt < 4; mt++) {
        int r = wm + mt * 16 + (lane & 15);
        aoff[mt] = (unsigned)r * 32u + (unsigned)((cbit ^ ((r >> 2) & 1)) * 16);
    }
    #pragma unroll
    for (int j = 0; j < 2; j++) {
        int r = wn + j * 16 + (lane & 15);
        boff[j] = 4096u + (unsigned)r * 32u
                + (unsigned)((cbit ^ ((r >> 2) & 1)) * 16);
    }

    issue(0, 0);
    issue(1, 1);

    for (int kb = 0; kb < nk; kb++) {
        int st = kb % 3;
        if (kb + 1 < nk)
            asm volatile("cp.async.wait_group 1;" ::: "memory");
        else
            asm volatile("cp.async.wait_group 0;" ::: "memory");
        __syncthreads();
        if (kb + 2 < nk) issue((kb + 2) % 3, kb + 2);   // prefetch early

        unsigned stg = sb + (unsigned)st * 16384u;
        #pragma unroll
        for (int sub = 0; sub < 2; sub++) {
            unsigned s0 = stg + (unsigned)sub * 8192u;
            unsigned bh[2][4];
            #pragma unroll
            for (int j = 0; j < 2; j++) ldsm4(bh[j], s0 + boff[j]);
            #pragma unroll
            for (int mt = 0; mt < 4; mt++) {
                unsigned ah[4];
                ldsm4(ah, s0 + aoff[mt]);
                #pragma unroll
                for (int j = 0; j < 2; j++) {
                    mma_fp16(acc[mt][2*j],   ah, bh[j][0], bh[j][2]);
                    mma_fp16(acc[mt][2*j+1], ah, bh[j][1], bh[j][3]);
                }
            }
        }
        __syncthreads();
    }

    #pragma unroll
    for (int mt = 0; mt < 4; mt++) {
        #pragma unroll
        for (int nt = 0; nt < 4; nt++) {
            int rr = m0 + wm + mt * 16 + (lane >> 2);
            int cc = n0 + wn + nt * 8 + (lane & 3) * 2;
            if (cc < Nn) {
                float bv0 = bias ? bias[cc] : 0.f;
                float bv1 = bias ? bias[cc + 1] : 0.f;
                C[(long)rr * ldc + cc]           = acc[mt][nt][0] + bv0;
                C[(long)rr * ldc + cc + 1]       = acc[mt][nt][1] + bv1;
                C[(long)(rr + 8) * ldc + cc]     = acc[mt][nt][2] + bv0;
                C[(long)(rr + 8) * ldc + cc + 1] = acc[mt][nt][3] + bv1;
            }
        }
    }
}

__global__ void __launch_bounds__(256, 2) gemm1_k() {
    gemm_hmma(g_A, NFC, g_W, NFC,
              g_c1p + (long)blockIdx.z * (BSZ * DW), DW, DW,
              blockIdx.y * 128, blockIdx.x * 128,
              (long)blockIdx.z * CH1, NK1, nullptr);
}

__global__ void __launch_bounds__(256, 2) gemm2_k(
    const float* __restrict__ biasb, float* __restrict__ out) {
    gemm_hmma(g_z, KP2, g_n, KP2,
              out, NENT, NENT,
              blockIdx.y * 128, blockIdx.x * 128, 0, NK2, biasb);
}

// ---------------- kernel 6: split-K reduce (fc bias cancels in BN1d) ----------
__global__ void __launch_bounds__(256) reduce_c1() {
    int idx = blockIdx.x * 256 + threadIdx.x;     // 800*256 == 204800
    float s = 0.f;
    #pragma unroll
    for (int z = 0; z < SK1; z++) s += g_c1p[z * (BSZ * DW) + idx];
    g_c1[idx] = s;
}

// ---------------- kernel 7: BN1d + ReLU -> fp16 (padded to KP2) ----------------
__global__ void __launch_bounds__(256) bn2_relu(
    const float* __restrict__ g2, const float* __restrict__ b2) {
    int d = blockIdx.x, t = threadIdx.x;          // d in [0,KP2)
    if (d >= DW) {
        for (int b = t; b < BSZ; b += 256) g_z[b * KP2 + d] = __float2half(0.f);
        return;
    }
    float s = 0.f, q = 0.f;
    for (int b = t; b < BSZ; b += 256) {
        float v = g_c1[b * DW + d];
        s += v; q += v * v;
    }
    __shared__ float ss[256], sq[256];
    ss[t] = s; sq[t] = q; __syncthreads();
    for (int st = 128; st > 0; st >>= 1) {
        if (t < st) { ss[t] += ss[t + st]; sq[t] += sq[t + st]; }
        __syncthreads();
    }
    float mean = ss[0] / BSZ;
    float var  = sq[0] / BSZ - mean * mean;
    float a = g2[d] * rsqrtf(var + EPSB);
    float bb = b2[d] - mean * a;
    for (int b = t; b < BSZ; b += 256) {
        float v = fmaxf(fmaf(a, g_c1[b * DW + d], bb), 0.f);
        g_z[b * KP2 + d] = __float2half(v);
    }
}

// ---------------- launch ----------------
extern "C" void kernel_launch(void* const* d_in, const int* in_sizes, int n_in,
                              void* d_out, int out_size) {
    const float* n_feats = (const float*)d_in[0];
    const float* r_feats = (const float*)d_in[1];
    const float* filt1   = (const float*)d_in[2];
    const float* filt2   = (const float*)d_in[3];
    const float* filt3   = (const float*)d_in[4];
    const float* bn0_g   = (const float*)d_in[5];
    const float* bn0_b   = (const float*)d_in[6];
    const float* bn1_g   = (const float*)d_in[7];
    const float* bn1_b   = (const float*)d_in[8];
    const float* bn2c_g  = (const float*)d_in[9];
    const float* bn2c_b  = (const float*)d_in[10];
    const float* bn3c_g  = (const float*)d_in[11];
    const float* bn3c_b  = (const float*)d_in[12];
    const float* se1_w1  = (const float*)d_in[13];
    const float* se1_w2  = (const float*)d_in[14];
    const float* se2_w1  = (const float*)d_in[15];
    const float* se2_w2  = (const float*)d_in[16];
    const float* se3_w1  = (const float*)d_in[17];
    const float* se3_w2  = (const float*)d_in[18];
    const float* att_w1  = (const float*)d_in[19];
    const float* att_w2  = (const float*)d_in[20];
    const float* fc_w    = (const float*)d_in[21];
    const float* bn2_g   = (const float*)d_in[23];
    const float* bn2_b   = (const float*)d_in[24];
    const float* bias_b  = (const float*)d_in[25];
    const int*   sub     = (const int*)d_in[26];
    const int*   rel     = (const int*)d_in[27];

    zero_stats<<<1, 3 * OC>>>();
    convW<<<22500, 256>>>(fc_w);
    convN<<<35000, 256>>>(n_feats);
    gather_bn0<<<BSZ, 128>>>(n_feats, r_feats, sub, rel);
    conv3_stats<<<dim3(BSZ, 3), 384>>>(filt1, filt2, filt3, rel, bn0_g, bn0_b);
    bnaff<<<1, 3 * OC>>>(bn1_g, bn1_b, bn2c_g, bn2c_b, bn3c_g, bn3c_b);
    gates<<<BSZ, 128>>>(se1_w1, se1_w2, se2_w1, se2_w2, se3_w1, se3_w2,
                        att_w1, att_w2);
    conv3_fused<<<dim3(BSZ, 3), 384>>>(filt1, filt2, filt3, rel, bn0_g, bn0_b);
    gemm1_k<<<dim3(2, BSZ / 128, SK1), 256>>>();
    reduce_c1<<<800, 256>>>();
    bn2_relu<<<KP2, 256>>>(bn2_g, bn2_b);
    gemm2_k<<<dim3((NENT + 127) / 128, BSZ / 128), 256>>>(bias_b, (float*)d_out);
}

// round 14
// speedup vs baseline: 1.0744x; 1.0545x over previous
#include <cuda_runtime.h>
#include <cuda_bf16.h>
#include <cuda_fp16.h>
#include <stdint.h>
#include <math.h>

// ---------------- problem constants ----------------
#define BSZ   1024
#define OC    96
#define DW    200          // d_embd
#define HW    400          // 20*20
#define NENT  40000
#define NFC   115200       // 3*96*400
#define EPSB  1e-5f
#define SK1   18
#define CH1   (NFC / SK1)  // 6400
#define NK1   (CH1 / 16)   // 400 k-steps of 16
#define KP2   208          // gemm2 K padded to mult of 16
#define NK2   (KP2 / 16)   // 13
#define WBLK  22500        // convW blocks (200*115200/4/256)
#define NBLK  32500        // convN blocks (40000*208/256)

// ---------------- device scratch ----------------
__device__ float g_x[BSZ * HW];
__device__ float g_bn0[2];
__device__ float g_bsum[3 * BSZ * OC];
__device__ float g_chsum[3 * OC];
__device__ float g_chsq[3 * OC];
__device__ float g_alpha[3 * OC];
__device__ float g_beta[3 * OC];
__device__ float g_scale[3 * BSZ * OC];
__device__ __align__(128) __half g_A [(long)BSZ * NFC];   // activations fp16
__device__ __align__(128) __half g_W [(long)DW * NFC];    // fc weight fp16
__device__ float g_c1p[SK1 * BSZ * DW];
__device__ float g_c1[BSZ * DW];
__device__ __align__(128) __half g_z [BSZ * KP2];         // BN2 output fp16
__device__ __align__(128) __half g_n [(long)NENT * KP2];  // n_feats fp16

// ---------------- PTX helpers ----------------
__device__ __forceinline__ void ldsm4(unsigned r[4], unsigned addr) {
    asm volatile("ldmatrix.sync.aligned.m8n8.x4.shared.b16 {%0,%1,%2,%3}, [%4];"
        : "=r"(r[0]), "=r"(r[1]), "=r"(r[2]), "=r"(r[3]) : "r"(addr));
}
__device__ __forceinline__ void mma_fp16(float* c, const unsigned* a,
                                         unsigned b0, unsigned b1) {
    asm volatile(
        "mma.sync.aligned.m16n8k16.row.col.f32.f16.f16.f32 "
        "{%0,%1,%2,%3}, {%4,%5,%6,%7}, {%8,%9}, {%0,%1,%2,%3};"
        : "+f"(c[0]), "+f"(c[1]), "+f"(c[2]), "+f"(c[3])
        : "r"(a[0]), "r"(a[1]), "r"(a[2]), "r"(a[3]), "r"(b0), "r"(b1));
}
__device__ __forceinline__ void cpa16(unsigned s, const void* g) {
    asm volatile("cp.async.ca.shared.global [%0], [%1], 16;" :: "r"(s), "l"(g));
}
__device__ __forceinline__ void cpa16z(unsigned s, const void* g, int srcsz) {
    asm volatile("cp.async.ca.shared.global [%0], [%1], 16, %2;"
                 :: "r"(s), "l"(g), "r"(srcsz));
}

// ---------------- kernel 0: zero atomics ----------------
__global__ void zero_stats() {
    int t = threadIdx.x;
    if (t < 2) g_bn0[t] = 0.f;
    if (t < 3 * OC) { g_chsum[t] = 0.f; g_chsq[t] = 0.f; }
}

// ---------------- merged convert kernel (runs on side stream) ----------------
__global__ void __launch_bounds__(256) convWN(const float* __restrict__ w,
                                             const float* __restrict__ nf) {
    long bid = blockIdx.x;
    if (bid < WBLK) {
        long i4 = bid * 256 + threadIdx.x;    // 4 floats each
        float4 v = ((const float4*)w)[i4];
        __half2 hh0, hh1;
        hh0.x = __float2half(v.x); hh0.y = __float2half(v.y);
        hh1.x = __float2half(v.z); hh1.y = __float2half(v.w);
        ((__half2*)g_W)[i4 * 2]     = hh0;
        ((__half2*)g_W)[i4 * 2 + 1] = hh1;
    } else {
        long t = (bid - WBLK) * 256 + threadIdx.x;   // 40000*208 elements
        int e = (int)(t / KP2), j = (int)(t - (long)e * KP2);
        float v = (j < DW) ? nf[(long)e * DW + j] : 0.f;
        g_n[t] = __float2half(v);
    }
}

// ---------------- kernel 1: gather + chequer + BN0 stats ----------------
__global__ void __launch_bounds__(128) gather_bn0(
    const float* __restrict__ n_feats, const float* __restrict__ r_feats,
    const int* __restrict__ sub, const int* __restrict__ rel)
{
    int b = blockIdx.x, t = threadIdx.x;
    int sb = sub[b], rb = rel[b];
    float s = 0.f, q = 0.f;
    for (int i = t; i < HW; i += 128) {
        float v = (i & 1) ? r_feats[rb * DW + (i >> 1)]
                          : n_feats[sb * DW + (i >> 1)];
        g_x[b * HW + i] = v;
        s += v; q += v * v;
    }
    __shared__ float ss[128], sq[128];
    ss[t] = s; sq[t] = q; __syncthreads();
    for (int st = 64; st > 0; st >>= 1) {
        if (t < st) { ss[t] += ss[t + st]; sq[t] += sq[t + st]; }
        __syncthreads();
    }
    if (t == 0) { atomicAdd(&g_bn0[0], ss[0]); atomicAdd(&g_bn0[1], sq[0]); }
}

// ---------------- conv helpers ----------------
__device__ __forceinline__ float conv_point(
    const float* __restrict__ xs, const float* __restrict__ fo,
    int brch, int h, int w)
{
    float acc = 0.f;
    if (brch == 0) {
        const float* xr = &xs[h * 20];
        acc = xr[w] * fo[2];
        if (w >= 2)  acc += xr[w - 2] * fo[0];
        if (w >= 1)  acc += xr[w - 1] * fo[1];
        if (w <= 18) acc += xr[w + 1] * fo[3];
        if (w <= 17) acc += xr[w + 2] * fo[4];
    } else if (brch == 1) {
        #pragma unroll
        for (int dh = 0; dh < 3; dh++) {
            int hh = h + dh - 1;
            if (hh < 0 || hh >= 20) continue;
            const float* xr = &xs[hh * 20];
            #pragma unroll
            for (int dw = 0; dw < 3; dw++) {
                int ww = w + dw - 1;
                if (ww >= 0 && ww < 20) acc += xr[ww] * fo[dh * 3 + dw];
            }
        }
    } else {
        #pragma unroll
        for (int dh = 0; dh < 5; dh++) {
            int hh = h + dh - 2;
            if (hh >= 0 && hh < 20) acc += xs[hh * 20 + w] * fo[dh];
        }
    }
    return acc;
}

// ---------------- kernel 2a: conv stats pass ----------------
__global__ void __launch_bounds__(384) conv3_stats(
    const float* __restrict__ f1, const float* __restrict__ f2,
    const float* __restrict__ f3, const int* __restrict__ rel,
    const float* __restrict__ bn0g, const float* __restrict__ bn0b)
{
    __shared__ float xs[HW];
    __shared__ float fs[OC * 9];
    int b = blockIdx.x, brch = blockIdx.y, t = threadIdx.x;

    float N0 = (float)BSZ * HW;
    float mean = g_bn0[0] / N0;
    float var  = g_bn0[1] / N0 - mean * mean;
    float a0 = bn0g[0] * rsqrtf(var + EPSB);
    float b0 = bn0b[0] - mean * a0;

    for (int i = t; i < HW; i += 384) xs[i] = g_x[b * HW + i] * a0 + b0;

    int rb = rel[b];
    int flen = (brch == 1) ? OC * 9 : OC * 5;
    int fstr = (brch == 1) ? 9 : 5;
    const float* fp = (brch == 0 ? f1 : (brch == 1 ? f2 : f3)) + (long)rb * flen;
    for (int i = t; i < flen; i += 384) fs[i] = fp[i];
    __syncthreads();

    int oc = t >> 2, q = t & 3;
    const float* fo = &fs[oc * fstr];
    float lsum = 0.f, lsq = 0.f;
    for (int p = q * 100; p < q * 100 + 100; p++) {
        int h = p / 20, w = p - h * 20;
        float acc = conv_point(xs, fo, brch, h, w);
        lsum += acc; lsq += acc * acc;
    }
    lsum += __shfl_down_sync(0xffffffffu, lsum, 2, 4);
    lsum += __shfl_down_sync(0xffffffffu, lsum, 1, 4);
    lsq  += __shfl_down_sync(0xffffffffu, lsq, 2, 4);
    lsq  += __shfl_down_sync(0xffffffffu, lsq, 1, 4);
    if (q == 0) {
        g_bsum[(brch * BSZ + b) * OC + oc] = lsum;
        atomicAdd(&g_chsum[brch * OC + oc], lsum);
        atomicAdd(&g_chsq[brch * OC + oc], lsq);
    }
}

// ---------------- kernel 3: BN affine ----------------
__global__ void bnaff(
    const float* __restrict__ g1, const float* __restrict__ b1,
    const float* __restrict__ g2, const float* __restrict__ b2,
    const float* __restrict__ g3, const float* __restrict__ b3)
{
    int i = threadIdx.x;
    if (i < 3 * OC) {
        int brch = i / OC, c = i - brch * OC;
        float N = (float)BSZ * HW;
        float mean = g_chsum[i] / N;
        float var  = g_chsq[i] / N - mean * mean;
        const float* g = brch == 0 ? g1 : (brch == 1 ? g2 : g3);
        const float* bb = brch == 0 ? b1 : (brch == 1 ? b2 : b3);
        float a = g[c] * rsqrtf(var + EPSB);
        g_alpha[i] = a;
        g_beta[i]  = bb[c] - mean * a;
    }
}

// ---------------- reductions ----------------
__device__ __forceinline__ float redsum128(float v, float* sm) {
    int t = threadIdx.x;
    sm[t] = v; __syncthreads();
    for (int s = 64; s > 0; s >>= 1) {
        if (t < s) sm[t] += sm[t + s];
        __syncthreads();
    }
    float r = sm[0]; __syncthreads();
    return r;
}
__device__ __forceinline__ float redmax128(float v, float* sm) {
    int t = threadIdx.x;
    sm[t] = v; __syncthreads();
    for (int s = 64; s > 0; s >>= 1) {
        if (t < s) sm[t] = fmaxf(sm[t], sm[t + s]);
        __syncthreads();
    }
    float r = sm[0]; __syncthreads();
    return r;
}

// ---------------- kernel 4: SE + ATT gates ----------------
__global__ void __launch_bounds__(128) gates(
    const float* __restrict__ s1w1, const float* __restrict__ s1w2,
    const float* __restrict__ s2w1, const float* __restrict__ s2w2,
    const float* __restrict__ s3w1, const float* __restrict__ s3w2,
    const float* __restrict__ aw1, const float* __restrict__ aw2)
{
    __shared__ float sm[128];
    int b = blockIdx.x, t = threadIdx.x;
    bool act = t < OC;
    int oc = act ? t : 0;

    const float* w1s[3] = {s1w1, s2w1, s3w1};
    const float* w2s[3] = {s1w2, s2w2, s3w2};

    float pool[3], seg[3];
    #pragma unroll
    for (int br = 0; br < 3; br++) {
        float p = fmaf(g_alpha[br * OC + oc],
                       g_bsum[(br * BSZ + b) * OC + oc] * (1.f / HW),
                       g_beta[br * OC + oc]);
        pool[br] = act ? p : 0.f;
    }
    #pragma unroll
    for (int br = 0; br < 3; br++) {
        float h0 = redsum128(act ? pool[br] * w1s[br][oc] : 0.f, sm);
        float h1 = redsum128(act ? pool[br] * w1s[br][OC + oc] : 0.f, sm);
        h0 = fmaxf(h0, 0.f); h1 = fmaxf(h1, 0.f);
        float lg = h0 * w2s[br][oc * 2] + h1 * w2s[br][oc * 2 + 1];
        seg[br] = 1.f / (1.f + expf(-lg));
    }
    float attp = seg[0] * pool[0] + seg[1] * pool[1] + seg[2] * pool[2];
    float a0 = fmaxf(redsum128(act ? attp * aw1[oc] : 0.f, sm), 0.f);
    float a1 = fmaxf(redsum128(act ? attp * aw1[OC + oc] : 0.f, sm), 0.f);

    float l[3], mx = -1e30f;
    #pragma unroll
    for (int br = 0; br < 3; br++) {
        l[br] = act ? (a0 * aw2[(br * OC + oc) * 2] + a1 * aw2[(br * OC + oc) * 2 + 1])
                    : -1e30f;
        mx = fmaxf(mx, l[br]);
    }
    float gm = redmax128(mx, sm);
    float e[3], le = 0.f;
    #pragma unroll
    for (int br = 0; br < 3; br++) { e[br] = expf(l[br] - gm); le += e[br]; }
    float S = redsum128(le, sm);
    if (act) {
        #pragma unroll
        for (int br = 0; br < 3; br++)
            g_scale[(br * BSZ + b) * OC + oc] = seg[br] * e[br] / S;
    }
}

// ---------------- kernel 2b: conv recompute + gate + relu -> fp16 (half2) ------
__global__ void __launch_bounds__(384) conv3_fused(
    const float* __restrict__ f1, const float* __restrict__ f2,
    const float* __restrict__ f3, const int* __restrict__ rel,
    const float* __restrict__ bn0g, const float* __restrict__ bn0b)
{
    __shared__ float xs[HW];
    __shared__ float fs[OC * 9];
    __shared__ float sA[OC], sBt[OC], sS[OC];
    int b = blockIdx.x, brch = blockIdx.y, t = threadIdx.x;

    float N0 = (float)BSZ * HW;
    float mean = g_bn0[0] / N0;
    float var  = g_bn0[1] / N0 - mean * mean;
    float a0 = bn0g[0] * rsqrtf(var + EPSB);
    float b0 = bn0b[0] - mean * a0;

    for (int i = t; i < HW; i += 384) xs[i] = g_x[b * HW + i] * a0 + b0;

    int rb = rel[b];
    int flen = (brch == 1) ? OC * 9 : OC * 5;
    int fstr = (brch == 1) ? 9 : 5;
    const float* fp = (brch == 0 ? f1 : (brch == 1 ? f2 : f3)) + (long)rb * flen;
    for (int i = t; i < flen; i += 384) fs[i] = fp[i];
    if (t < OC) {
        sA[t]  = g_alpha[brch * OC + t];
        sBt[t] = g_beta[brch * OC + t];
        sS[t]  = g_scale[(brch * BSZ + b) * OC + t];
    }
    __syncthreads();

    long obase2 = ((long)b * NFC + (long)brch * (OC * HW)) >> 1;  // in half2 units
    for (int i2 = t; i2 < OC * HW / 2; i2 += 384) {
        int oc = i2 / (HW / 2);
        int p = (i2 - oc * (HW / 2)) * 2;
        int h = p / 20, w = p - h * 20;    // p even; p, p+1 same row when w<19
        const float* fo = &fs[oc * fstr];
        float acc0 = conv_point(xs, fo, brch, h, w);
        int h1 = (w + 1 < 20) ? h : h + 1;
        int w1 = (w + 1 < 20) ? w + 1 : 0;
        float acc1 = conv_point(xs, fo, brch, h1, w1);
        float v0 = fmaxf(fmaf(sA[oc], acc0, sBt[oc]) * sS[oc], 0.f);
        float v1 = fmaxf(fmaf(sA[oc], acc1, sBt[oc]) * sS[oc], 0.f);
        __half2 hv; hv.x = __float2half(v0); hv.y = __float2half(v1);
        ((__half2*)g_A)[obase2 + i2] = hv;
    }
}

// ---------------- HMMA fp16 GEMM: 128x128 tile, kstep16, 3 stages, occ-2 --------
// 2 planes (A, B); smem stage = 8KB, 3 stages = 24KB.
__device__ __forceinline__ void gemm_hmma(
    const __half* __restrict__ A, long lda,
    const __half* __restrict__ B, long ldb,
    float* __restrict__ C, long ldc, int Nn,
    int m0, int n0, long k0, int nk, const float* __restrict__ bias)
{
    __shared__ __align__(16) char smem[24576];
    unsigned sb = (unsigned)__cvta_generic_to_shared(smem);
    int tid = threadIdx.x, lane = tid & 31, wid = tid >> 5;
    int wm = (wid >> 2) * 64, wn = (wid & 3) * 32;

    float acc[4][4][4];
    #pragma unroll
    for (int i = 0; i < 4; i++)
        #pragma unroll
        for (int j = 0; j < 4; j++)
            #pragma unroll
            for (int k = 0; k < 4; k++) acc[i][j][k] = 0.f;

    auto issue = [&](int stg_, int kb_) {
        unsigned s0_ = sb + (unsigned)stg_ * 8192u;
        long kk_ = k0 + (long)kb_ * 16;
        #pragma unroll
        for (int ii = 0; ii < 2; ii++) {
            int i_ = tid + ii * 256;
            int pl_ = i_ >> 8, r_ = (i_ >> 1) & 127, c_ = i_ & 1;
            unsigned sw_ = s0_ + (unsigned)pl_ * 4096u + (unsigned)r_ * 32u
                         + (unsigned)((c_ ^ ((r_ >> 2) & 1)) * 16);
            if (pl_ == 0) {
                cpa16(sw_, A + (long)(m0 + r_) * lda + kk_ + c_ * 8);
            } else {
                int ok_ = ((n0 + r_) < Nn) ? 16 : 0;
                cpa16z(sw_, B + (long)(n0 + r_) * ldb + kk_ + c_ * 8, ok_);
            }
        }
        asm volatile("cp.async.commit_group;" ::: "memory");
    };

    int cbit = lane >> 4;
    unsigned aoff[4], boff[2];
    #pragma unroll
    for (int mt = 0; mt < 4; mt++) {
        int r = wm + mt * 16 + (lane & 15);
        aoff[mt] = (unsigned)r * 32u + (unsigned)((cbit ^ ((r >> 2) & 1)) * 16);
    }
    #pragma unroll
    for (int j = 0; j < 2; j++) {
        int r = wn + j * 16 + (lane & 15);
        boff[j] = 4096u + (unsigned)r * 32u
                + (unsigned)((cbit ^ ((r >> 2) & 1)) * 16);
    }

    issue(0, 0);
    issue(1, 1);

    for (int kb = 0; kb < nk; kb++) {
        int st = kb % 3;
        if (kb + 1 < nk)
            asm volatile("cp.async.wait_group 1;" ::: "memory");
        else
            asm volatile("cp.async.wait_group 0;" ::: "memory");
        __syncthreads();
        if (kb + 2 < nk) issue((kb + 2) % 3, kb + 2);   // prefetch early

        unsigned s0 = sb + (unsigned)st * 8192u;
        unsigned bh[2][4];
        #pragma unroll
        for (int j = 0; j < 2; j++) ldsm4(bh[j], s0 + boff[j]);
        #pragma unroll
        for (int mt = 0; mt < 4; mt++) {
            unsigned ah[4];
            ldsm4(ah, s0 + aoff[mt]);
            #pragma unroll
            for (int j = 0; j < 2; j++) {
                mma_fp16(acc[mt][2*j],   ah, bh[j][0], bh[j][2]);
                mma_fp16(acc[mt][2*j+1], ah, bh[j][1], bh[j][3]);
            }
        }
        __syncthreads();
    }

    #pragma unroll
    for (int mt = 0; mt < 4; mt++) {
        #pragma unroll
        for (int nt = 0; nt < 4; nt++) {
            int rr = m0 + wm + mt * 16 + (lane >> 2);
            int cc = n0 + wn + nt * 8 + (lane & 3) * 2;
            if (cc < Nn) {
                float bv0 = bias ? bias[cc] : 0.f;
                float bv1 = bias ? bias[cc + 1] : 0.f;
                C[(long)rr * ldc + cc]           = acc[mt][nt][0] + bv0;
                C[(long)rr * ldc + cc + 1]       = acc[mt][nt][1] + bv1;
                C[(long)(rr + 8) * ldc + cc]     = acc[mt][nt][2] + bv0;
                C[(long)(rr + 8) * ldc + cc + 1] = acc[mt][nt][3] + bv1;
            }
        }
    }
}

__global__ void __launch_bounds__(256, 2) gemm1_k() {
    gemm_hmma(g_A, NFC, g_W, NFC,
              g_c1p + (long)blockIdx.z * (BSZ * DW), DW, DW,
              blockIdx.y * 128, blockIdx.x * 128,
              (long)blockIdx.z * CH1, NK1, nullptr);
}

__global__ void __launch_bounds__(256, 2) gemm2_k(
    const float* __restrict__ biasb, float* __restrict__ out) {
    gemm_hmma(g_z, KP2, g_n, KP2,
              out, NENT, NENT,
              blockIdx.y * 128, blockIdx.x * 128, 0, NK2, biasb);
}

// ---------------- kernel 6: split-K reduce (fc bias cancels in BN1d) ----------
__global__ void __launch_bounds__(256) reduce_c1() {
    int idx = blockIdx.x * 256 + threadIdx.x;     // 800*256 == 204800
    float s = 0.f;
    #pragma unroll
    for (int z = 0; z < SK1; z++) s += g_c1p[z * (BSZ * DW) + idx];
    g_c1[idx] = s;
}

// ---------------- kernel 7: BN1d + ReLU -> fp16 (padded to KP2) ----------------
__global__ void __launch_bounds__(256) bn2_relu(
    const float* __restrict__ g2, const float* __restrict__ b2) {
    int d = blockIdx.x, t = threadIdx.x;          // d in [0,KP2)
    if (d >= DW) {
        for (int b = t; b < BSZ; b += 256) g_z[b * KP2 + d] = __float2half(0.f);
        return;
    }
    float s = 0.f, q = 0.f;
    for (int b = t; b < BSZ; b += 256) {
        float v = g_c1[b * DW + d];
        s += v; q += v * v;
    }
    __shared__ float ss[256], sq[256];
    ss[t] = s; sq[t] = q; __syncthreads();
    for (int st = 128; st > 0; st >>= 1) {
        if (t < st) { ss[t] += ss[t + st]; sq[t] += sq[t + st]; }
        __syncthreads();
    }
    float mean = ss[0] / BSZ;
    float var  = sq[0] / BSZ - mean * mean;
    float a = g2[d] * rsqrtf(var + EPSB);
    float bb = b2[d] - mean * a;
    for (int b = t; b < BSZ; b += 256) {
        float v = fmaxf(fmaf(a, g_c1[b * DW + d], bb), 0.f);
        g_z[b * KP2 + d] = __float2half(v);
    }
}

// ---------------- launch ----------------
extern "C" void kernel_launch(void* const* d_in, const int* in_sizes, int n_in,
                              void* d_out, int out_size) {
    const float* n_feats = (const float*)d_in[0];
    const float* r_feats = (const float*)d_in[1];
    const float* filt1   = (const float*)d_in[2];
    const float* filt2   = (const float*)d_in[3];
    const float* filt3   = (const float*)d_in[4];
    const float* bn0_g   = (const float*)d_in[5];
    const float* bn0_b   = (const float*)d_in[6];
    const float* bn1_g   = (const float*)d_in[7];
    const float* bn1_b   = (const float*)d_in[8];
    const float* bn2c_g  = (const float*)d_in[9];
    const float* bn2c_b  = (const float*)d_in[10];
    const float* bn3c_g  = (const float*)d_in[11];
    const float* bn3c_b  = (const float*)d_in[12];
    const float* se1_w1  = (const float*)d_in[13];
    const float* se1_w2  = (const float*)d_in[14];
    const float* se2_w1  = (const float*)d_in[15];
    const float* se2_w2  = (const float*)d_in[16];
    const float* se3_w1  = (const float*)d_in[17];
    const float* se3_w2  = (const float*)d_in[18];
    const float* att_w1  = (const float*)d_in[19];
    const float* att_w2  = (const float*)d_in[20];
    const float* fc_w    = (const float*)d_in[21];
    const float* bn2_g   = (const float*)d_in[23];
    const float* bn2_b   = (const float*)d_in[24];
    const float* bias_b  = (const float*)d_in[25];
    const int*   sub     = (const int*)d_in[26];
    const int*   rel     = (const int*)d_in[27];

    // fork/join side stream for the input-only converts
    cudaStream_t s2;
    cudaStreamCreateWithFlags(&s2, cudaStreamNonBlocking);
    cudaEvent_t e1, e2;
    cudaEventCreateWithFlags(&e1, cudaEventDisableTiming);
    cudaEventCreateWithFlags(&e2, cudaEventDisableTiming);

    zero_stats<<<1, 3 * OC>>>();
    cudaEventRecord(e1, 0);
    cudaStreamWaitEvent(s2, e1, 0);
    convWN<<<WBLK + NBLK, 256, 0, s2>>>(fc_w, n_feats);

    gather_bn0<<<BSZ, 128>>>(n_feats, r_feats, sub, rel);
    conv3_stats<<<dim3(BSZ, 3), 384>>>(filt1, filt2, filt3, rel, bn0_g, bn0_b);
    bnaff<<<1, 3 * OC>>>(bn1_g, bn1_b, bn2c_g, bn2c_b, bn3c_g, bn3c_b);
    gates<<<BSZ, 128>>>(se1_w1, se1_w2, se2_w1, se2_w2, se3_w1, se3_w2,
                        att_w1, att_w2);
    conv3_fused<<<dim3(BSZ, 3), 384>>>(filt1, filt2, filt3, rel, bn0_g, bn0_b);

    cudaEventRecord(e2, s2);
    cudaStreamWaitEvent(0, e2, 0);

    gemm1_k<<<dim3(2, BSZ / 128, SK1), 256>>>();
    reduce_c1<<<800, 256>>>();
    bn2_relu<<<KP2, 256>>>(bn2_g, bn2_b);
    gemm2_k<<<dim3((NENT + 127) / 128, BSZ / 128), 256>>>(bias_b, (float*)d_out);
}

// round 15
// speedup vs baseline: 1.6404x; 1.5268x over previous
#include <cuda_runtime.h>
#include <cuda_bf16.h>
#include <cuda_fp16.h>
#include <stdint.h>
#include <math.h>

// ---------------- problem constants ----------------
#define BSZ   1024
#define OC    96
#define DW    200          // d_embd
#define HW    400          // 20*20
#define NENT  40000
#define NFC   115200       // 3*96*400
#define EPSB  1e-5f
#define SK1   18
#define CH1   (NFC / SK1)  // 6400
#define NK1   (CH1 / 16)   // 400 k-steps of 16
#define KP2   208          // gemm2 K padded to mult of 16
#define NK2   (KP2 / 16)   // 13
#define WBLK  22500
#define NBLK  32500
#define XP    24           // padded image dim (2-halo)

// ---------------- device scratch ----------------
__device__ float g_x[BSZ * HW];
__device__ float g_bn0[2];
__device__ float g_bsum[3 * BSZ * OC];
__device__ float g_chsum[3 * OC];
__device__ float g_chsq[3 * OC];
__device__ float g_alpha[3 * OC];
__device__ float g_beta[3 * OC];
__device__ float g_scale[3 * BSZ * OC];
__device__ __align__(128) __half g_A [(long)BSZ * NFC];
__device__ __align__(128) __half g_W [(long)DW * NFC];
__device__ float g_c1p[SK1 * BSZ * DW];
__device__ float g_c1[BSZ * DW];
__device__ __align__(128) __half g_z [BSZ * KP2];
__device__ __align__(128) __half g_n [(long)NENT * KP2];

// ---------------- PTX helpers ----------------
__device__ __forceinline__ void ldsm4(unsigned r[4], unsigned addr) {
    asm volatile("ldmatrix.sync.aligned.m8n8.x4.shared.b16 {%0,%1,%2,%3}, [%4];"
        : "=r"(r[0]), "=r"(r[1]), "=r"(r[2]), "=r"(r[3]) : "r"(addr));
}
__device__ __forceinline__ void mma_fp16(float* c, const unsigned* a,
                                         unsigned b0, unsigned b1) {
    asm volatile(
        "mma.sync.aligned.m16n8k16.row.col.f32.f16.f16.f32 "
        "{%0,%1,%2,%3}, {%4,%5,%6,%7}, {%8,%9}, {%0,%1,%2,%3};"
        : "+f"(c[0]), "+f"(c[1]), "+f"(c[2]), "+f"(c[3])
        : "r"(a[0]), "r"(a[1]), "r"(a[2]), "r"(a[3]), "r"(b0), "r"(b1));
}
__device__ __forceinline__ void cpa16(unsigned s, const void* g) {
    asm volatile("cp.async.ca.shared.global [%0], [%1], 16;" :: "r"(s), "l"(g));
}
__device__ __forceinline__ void cpa16z(unsigned s, const void* g, int srcsz) {
    asm volatile("cp.async.ca.shared.global [%0], [%1], 16, %2;"
                 :: "r"(s), "l"(g), "r"(srcsz));
}

// ---------------- kernel 0: zero atomics ----------------
__global__ void zero_stats() {
    int t = threadIdx.x;
    if (t < 2) g_bn0[t] = 0.f;
    if (t < 3 * OC) { g_chsum[t] = 0.f; g_chsq[t] = 0.f; }
}

// ---------------- merged convert kernel (side stream) ----------------
__global__ void __launch_bounds__(256) convWN(const float* __restrict__ w,
                                             const float* __restrict__ nf) {
    long bid = blockIdx.x;
    if (bid < WBLK) {
        long i4 = bid * 256 + threadIdx.x;
        float4 v = ((const float4*)w)[i4];
        __half2 hh0, hh1;
        hh0.x = __float2half(v.x); hh0.y = __float2half(v.y);
        hh1.x = __float2half(v.z); hh1.y = __float2half(v.w);
        ((__half2*)g_W)[i4 * 2]     = hh0;
        ((__half2*)g_W)[i4 * 2 + 1] = hh1;
    } else {
        long t = (bid - WBLK) * 256 + threadIdx.x;
        int e = (int)(t / KP2), j = (int)(t - (long)e * KP2);
        float v = (j < DW) ? nf[(long)e * DW + j] : 0.f;
        g_n[t] = __float2half(v);
    }
}

// ---------------- kernel 1: gather + chequer + BN0 stats ----------------
__global__ void __launch_bounds__(128) gather_bn0(
    const float* __restrict__ n_feats, const float* __restrict__ r_feats,
    const int* __restrict__ sub, const int* __restrict__ rel)
{
    int b = blockIdx.x, t = threadIdx.x;
    int sb = sub[b], rb = rel[b];
    float s = 0.f, q = 0.f;
    for (int i = t; i < HW; i += 128) {
        float v = (i & 1) ? r_feats[rb * DW + (i >> 1)]
                          : n_feats[sb * DW + (i >> 1)];
        g_x[b * HW + i] = v;
        s += v; q += v * v;
    }
    __shared__ float ss[128], sq[128];
    ss[t] = s; sq[t] = q; __syncthreads();
    for (int st = 64; st > 0; st >>= 1) {
        if (t < st) { ss[t] += ss[t + st]; sq[t] += sq[t + st]; }
        __syncthreads();
    }
    if (t == 0) { atomicAdd(&g_bn0[0], ss[0]); atomicAdd(&g_bn0[1], sq[0]); }
}

// ---------------- padded-image loader (shared by conv kernels) ----------------
__device__ __forceinline__ void load_padded(float* xs, int b, float a0, float b0,
                                            int t, int nthr) {
    for (int i = t; i < XP * XP; i += nthr) xs[i] = 0.f;
    __syncthreads();
    for (int i = t; i < HW; i += nthr) {
        int h = i / 20, w = i - h * 20;
        xs[(h + 2) * XP + (w + 2)] = g_x[b * HW + i] * a0 + b0;
    }
    __syncthreads();
}

#define X(h_, w_) xs[((h_) + 2) * XP + ((w_) + 2)]

// ---------------- kernel 2a: conv stats pass (sliding windows, no guards) ------
__global__ void __launch_bounds__(384) conv3_stats(
    const float* __restrict__ f1, const float* __restrict__ f2,
    const float* __restrict__ f3, const int* __restrict__ rel,
    const float* __restrict__ bn0g, const float* __restrict__ bn0b)
{
    __shared__ float xs[XP * XP];
    __shared__ float fs[OC * 9];
    int b = blockIdx.x, brch = blockIdx.y, t = threadIdx.x;

    float N0 = (float)BSZ * HW;
    float mean = g_bn0[0] / N0;
    float var  = g_bn0[1] / N0 - mean * mean;
    float a0 = bn0g[0] * rsqrtf(var + EPSB);
    float b0 = bn0b[0] - mean * a0;

    int rb = rel[b];
    int flen = (brch == 1) ? OC * 9 : OC * 5;
    int fstr = (brch == 1) ? 9 : 5;
    const float* fp = (brch == 0 ? f1 : (brch == 1 ? f2 : f3)) + (long)rb * flen;
    for (int i = t; i < flen; i += 384) fs[i] = fp[i];
    load_padded(xs, b, a0, b0, t, 384);

    int oc = t >> 2, q = t & 3;
    int h0 = q * 5;
    const float* fo = &fs[oc * fstr];
    float lsum = 0.f, lsq = 0.f;

    if (brch == 0) {                 // 1x5 horizontal
        float k0 = fo[0], k1 = fo[1], k2 = fo[2], k3 = fo[3], k4 = fo[4];
        #pragma unroll
        for (int hh = 0; hh < 5; hh++) {
            int h = h0 + hh;
            float xm2 = X(h, -2), xm1 = X(h, -1), x0 = X(h, 0), xp1 = X(h, 1);
            #pragma unroll 5
            for (int w = 0; w < 20; w++) {
                float xp2 = X(h, w + 2);
                float acc = xm2 * k0 + xm1 * k1 + x0 * k2 + xp1 * k3 + xp2 * k4;
                lsum += acc; lsq += acc * acc;
                xm2 = xm1; xm1 = x0; x0 = xp1; xp1 = xp2;
            }
        }
    } else if (brch == 1) {          // 3x3
        float k0=fo[0],k1=fo[1],k2=fo[2],k3=fo[3],k4=fo[4],k5=fo[5],k6=fo[6],k7=fo[7],k8=fo[8];
        #pragma unroll
        for (int hh = 0; hh < 5; hh++) {
            int h = h0 + hh;
            float u0 = X(h-1,-1), u1 = X(h-1,0);
            float c0 = X(h,-1),   c1 = X(h,0);
            float d0 = X(h+1,-1), d1 = X(h+1,0);
            #pragma unroll 5
            for (int w = 0; w < 20; w++) {
                float u2 = X(h-1, w+1), c2 = X(h, w+1), d2 = X(h+1, w+1);
                float acc = u0*k0 + u1*k1 + u2*k2
                          + c0*k3 + c1*k4 + c2*k5
                          + d0*k6 + d1*k7 + d2*k8;
                lsum += acc; lsq += acc * acc;
                u0=u1; u1=u2; c0=c1; c1=c2; d0=d1; d1=d2;
            }
        }
    } else {                         // 5x1 vertical
        float k0 = fo[0], k1 = fo[1], k2 = fo[2], k3 = fo[3], k4 = fo[4];
        #pragma unroll 4
        for (int w = 0; w < 20; w++) {
            float r0 = X(h0-2,w), r1 = X(h0-1,w), r2 = X(h0,w), r3 = X(h0+1,w);
            #pragma unroll
            for (int hh = 0; hh < 5; hh++) {
                float r4 = X(h0+hh+2, w);
                float acc = r0*k0 + r1*k1 + r2*k2 + r3*k3 + r4*k4;
                lsum += acc; lsq += acc * acc;
                r0 = r1; r1 = r2; r2 = r3; r3 = r4;
            }
        }
    }

    lsum += __shfl_down_sync(0xffffffffu, lsum, 2, 4);
    lsum += __shfl_down_sync(0xffffffffu, lsum, 1, 4);
    lsq  += __shfl_down_sync(0xffffffffu, lsq, 2, 4);
    lsq  += __shfl_down_sync(0xffffffffu, lsq, 1, 4);
    if (q == 0) {
        g_bsum[(brch * BSZ + b) * OC + oc] = lsum;
        atomicAdd(&g_chsum[brch * OC + oc], lsum);
        atomicAdd(&g_chsq[brch * OC + oc], lsq);
    }
}

// ---------------- kernel 3: BN affine ----------------
__global__ void bnaff(
    const float* __restrict__ g1, const float* __restrict__ b1,
    const float* __restrict__ g2, const float* __restrict__ b2,
    const float* __restrict__ g3, const float* __restrict__ b3)
{
    int i = threadIdx.x;
    if (i < 3 * OC) {
        int brch = i / OC, c = i - brch * OC;
        float N = (float)BSZ * HW;
        float mean = g_chsum[i] / N;
        float var  = g_chsq[i] / N - mean * mean;
        const float* g = brch == 0 ? g1 : (brch == 1 ? g2 : g3);
        const float* bb = brch == 0 ? b1 : (brch == 1 ? b2 : b3);
        float a = g[c] * rsqrtf(var + EPSB);
        g_alpha[i] = a;
        g_beta[i]  = bb[c] - mean * a;
    }
}

// ---------------- reductions ----------------
__device__ __forceinline__ float redsum128(float v, float* sm) {
    int t = threadIdx.x;
    sm[t] = v; __syncthreads();
    for (int s = 64; s > 0; s >>= 1) {
        if (t < s) sm[t] += sm[t + s];
        __syncthreads();
    }
    float r = sm[0]; __syncthreads();
    return r;
}
__device__ __forceinline__ float redmax128(float v, float* sm) {
    int t = threadIdx.x;
    sm[t] = v; __syncthreads();
    for (int s = 64; s > 0; s >>= 1) {
        if (t < s) sm[t] = fmaxf(sm[t], sm[t + s]);
        __syncthreads();
    }
    float r = sm[0]; __syncthreads();
    return r;
}

// ---------------- kernel 4: SE + ATT gates ----------------
__global__ void __launch_bounds__(128) gates(
    const float* __restrict__ s1w1, const float* __restrict__ s1w2,
    const float* __restrict__ s2w1, const float* __restrict__ s2w2,
    const float* __restrict__ s3w1, const float* __restrict__ s3w2,
    const float* __restrict__ aw1, const float* __restrict__ aw2)
{
    __shared__ float sm[128];
    int b = blockIdx.x, t = threadIdx.x;
    bool act = t < OC;
    int oc = act ? t : 0;

    const float* w1s[3] = {s1w1, s2w1, s3w1};
    const float* w2s[3] = {s1w2, s2w2, s3w2};

    float pool[3], seg[3];
    #pragma unroll
    for (int br = 0; br < 3; br++) {
        float p = fmaf(g_alpha[br * OC + oc],
                       g_bsum[(br * BSZ + b) * OC + oc] * (1.f / HW),
                       g_beta[br * OC + oc]);
        pool[br] = act ? p : 0.f;
    }
    #pragma unroll
    for (int br = 0; br < 3; br++) {
        float h0 = redsum128(act ? pool[br] * w1s[br][oc] : 0.f, sm);
        float h1 = redsum128(act ? pool[br] * w1s[br][OC + oc] : 0.f, sm);
        h0 = fmaxf(h0, 0.f); h1 = fmaxf(h1, 0.f);
        float lg = h0 * w2s[br][oc * 2] + h1 * w2s[br][oc * 2 + 1];
        seg[br] = 1.f / (1.f + expf(-lg));
    }
    float attp = seg[0] * pool[0] + seg[1] * pool[1] + seg[2] * pool[2];
    float a0 = fmaxf(redsum128(act ? attp * aw1[oc] : 0.f, sm), 0.f);
    float a1 = fmaxf(redsum128(act ? attp * aw1[OC + oc] : 0.f, sm), 0.f);

    float l[3], mx = -1e30f;
    #pragma unroll
    for (int br = 0; br < 3; br++) {
        l[br] = act ? (a0 * aw2[(br * OC + oc) * 2] + a1 * aw2[(br * OC + oc) * 2 + 1])
                    : -1e30f;
        mx = fmaxf(mx, l[br]);
    }
    float gm = redmax128(mx, sm);
    float e[3], le = 0.f;
    #pragma unroll
    for (int br = 0; br < 3; br++) { e[br] = expf(l[br] - gm); le += e[br]; }
    float S = redsum128(le, sm);
    if (act) {
        #pragma unroll
        for (int br = 0; br < 3; br++)
            g_scale[(br * BSZ + b) * OC + oc] = seg[br] * e[br] / S;
    }
}

// ---------------- kernel 2b: conv + gate + relu -> smem stage -> coalesced A ---
__global__ void __launch_bounds__(384) conv3_fused(
    const float* __restrict__ f1, const float* __restrict__ f2,
    const float* __restrict__ f3, const int* __restrict__ rel,
    const float* __restrict__ bn0g, const float* __restrict__ bn0b)
{
    __shared__ float xs[XP * XP];
    __shared__ float fs[OC * 9];
    __shared__ float sA[OC], sBt[OC], sS[OC];
    extern __shared__ __half ybuf[];    // OC*HW halves = 76800 B
    int b = blockIdx.x, brch = blockIdx.y, t = threadIdx.x;

    float N0 = (float)BSZ * HW;
    float mean = g_bn0[0] / N0;
    float var  = g_bn0[1] / N0 - mean * mean;
    float a0 = bn0g[0] * rsqrtf(var + EPSB);
    float b0 = bn0b[0] - mean * a0;

    int rb = rel[b];
    int flen = (brch == 1) ? OC * 9 : OC * 5;
    int fstr = (brch == 1) ? 9 : 5;
    const float* fp = (brch == 0 ? f1 : (brch == 1 ? f2 : f3)) + (long)rb * flen;
    for (int i = t; i < flen; i += 384) fs[i] = fp[i];
    if (t < OC) {
        sA[t]  = g_alpha[brch * OC + t];
        sBt[t] = g_beta[brch * OC + t];
        sS[t]  = g_scale[(brch * BSZ + b) * OC + t];
    }
    load_padded(xs, b, a0, b0, t, 384);

    int oc = t >> 2, q = t & 3;
    int h0 = q * 5;
    const float* fo = &fs[oc * fstr];
    float ga = sA[oc], gb = sBt[oc], gs = sS[oc];
    __half* yrow = &ybuf[oc * HW];

    #define EMIT(acc_, h_, w_) do {                                    \
        float v_ = fmaxf(fmaf(ga, (acc_), gb) * gs, 0.f);              \
        yrow[(h_) * 20 + (w_)] = __float2half(v_);                     \
    } while (0)

    if (brch == 0) {
        float k0 = fo[0], k1 = fo[1], k2 = fo[2], k3 = fo[3], k4 = fo[4];
        #pragma unroll
        for (int hh = 0; hh < 5; hh++) {
            int h = h0 + hh;
            float xm2 = X(h, -2), xm1 = X(h, -1), x0 = X(h, 0), xp1 = X(h, 1);
            #pragma unroll 5
            for (int w = 0; w < 20; w++) {
                float xp2 = X(h, w + 2);
                float acc = xm2 * k0 + xm1 * k1 + x0 * k2 + xp1 * k3 + xp2 * k4;
                EMIT(acc, h, w);
                xm2 = xm1; xm1 = x0; x0 = xp1; xp1 = xp2;
            }
        }
    } else if (brch == 1) {
        float k0=fo[0],k1=fo[1],k2=fo[2],k3=fo[3],k4=fo[4],k5=fo[5],k6=fo[6],k7=fo[7],k8=fo[8];
        #pragma unroll
        for (int hh = 0; hh < 5; hh++) {
            int h = h0 + hh;
            float u0 = X(h-1,-1), u1 = X(h-1,0);
            float c0 = X(h,-1),   c1 = X(h,0);
            float d0 = X(h+1,-1), d1 = X(h+1,0);
            #pragma unroll 5
            for (int w = 0; w < 20; w++) {
                float u2 = X(h-1, w+1), c2 = X(h, w+1), d2 = X(h+1, w+1);
                float acc = u0*k0 + u1*k1 + u2*k2
                          + c0*k3 + c1*k4 + c2*k5
                          + d0*k6 + d1*k7 + d2*k8;
                EMIT(acc, h, w);
                u0=u1; u1=u2; c0=c1; c1=c2; d0=d1; d1=d2;
            }
        }
    } else {
        float k0 = fo[0], k1 = fo[1], k2 = fo[2], k3 = fo[3], k4 = fo[4];
        #pragma unroll 4
        for (int w = 0; w < 20; w++) {
            float r0 = X(h0-2,w), r1 = X(h0-1,w), r2 = X(h0,w), r3 = X(h0+1,w);
            #pragma unroll
            for (int hh = 0; hh < 5; hh++) {
                float r4 = X(h0+hh+2, w);
                float acc = r0*k0 + r1*k1 + r2*k2 + r3*k3 + r4*k4;
                EMIT(acc, h0 + hh, w);
                r0 = r1; r1 = r2; r2 = r3; r3 = r4;
            }
        }
    }
    #undef EMIT
    __syncthreads();

    // coalesced copy: 38400 halves = 4800 uint4
    const uint4* src = (const uint4*)ybuf;
    uint4* dst = (uint4*)(g_A + (long)b * NFC + (long)brch * (OC * HW));
    for (int i = t; i < OC * HW / 8; i += 384) dst[i] = src[i];
}

// ---------------- HMMA fp16 GEMM: 128x128 tile, kstep16, 3 stages, occ-2 --------
__device__ __forceinline__ void gemm_hmma(
    const __half* __restrict__ A, long lda,
    const __half* __restrict__ B, long ldb,
    float* __restrict__ C, long ldc, int Nn,
    int m0, int n0, long k0, int nk, const float* __restrict__ bias)
{
    __shared__ __align__(16) char smem[24576];
    unsigned sb = (unsigned)__cvta_generic_to_shared(smem);
    int tid = threadIdx.x, lane = tid & 31, wid = tid >> 5;
    int wm = (wid >> 2) * 64, wn = (wid & 3) * 32;

    float acc[4][4][4];
    #pragma unroll
    for (int i = 0; i < 4; i++)
        #pragma unroll
        for (int j = 0; j < 4; j++)
            #pragma unroll
            for (int k = 0; k < 4; k++) acc[i][j][k] = 0.f;

    auto issue = [&](int stg_, int kb_) {
        unsigned s0_ = sb + (unsigned)stg_ * 8192u;
        long kk_ = k0 + (long)kb_ * 16;
        #pragma unroll
        for (int ii = 0; ii < 2; ii++) {
            int i_ = tid + ii * 256;
            int pl_ = i_ >> 8, r_ = (i_ >> 1) & 127, c_ = i_ & 1;
            unsigned sw_ = s0_ + (unsigned)pl_ * 4096u + (unsigned)r_ * 32u
                         + (unsigned)((c_ ^ ((r_ >> 2) & 1)) * 16);
            if (pl_ == 0) {
                cpa16(sw_, A + (long)(m0 + r_) * lda + kk_ + c_ * 8);
            } else {
                int ok_ = ((n0 + r_) < Nn) ? 16 : 0;
                cpa16z(sw_, B + (long)(n0 + r_) * ldb + kk_ + c_ * 8, ok_);
            }
        }
        asm volatile("cp.async.commit_group;" ::: "memory");
    };

    int cbit = lane >> 4;
    unsigned aoff[4], boff[2];
    #pragma unroll
    for (int mt = 0; mt < 4; mt++) {
        int r = wm + mt * 16 + (lane & 15);
        aoff[mt] = (unsigned)r * 32u + (unsigned)((cbit ^ ((r >> 2) & 1)) * 16);
    }
    #pragma unroll
    for (int j = 0; j < 2; j++) {
        int r = wn + j * 16 + (lane & 15);
        boff[j] = 4096u + (unsigned)r * 32u
                + (unsigned)((cbit ^ ((r >> 2) & 1)) * 16);
    }

    issue(0, 0);
    issue(1, 1);

    for (int kb = 0; kb < nk; kb++) {
        int st = kb % 3;
        if (kb + 1 < nk)
            asm volatile("cp.async.wait_group 1;" ::: "memory");
        else
            asm volatile("cp.async.wait_group 0;" ::: "memory");
        __syncthreads();
        if (kb + 2 < nk) issue((kb + 2) % 3, kb + 2);

        unsigned s0 = sb + (unsigned)st * 8192u;
        unsigned bh[2][4];
        #pragma unroll
        for (int j = 0; j < 2; j++) ldsm4(bh[j], s0 + boff[j]);
        #pragma unroll
        for (int mt = 0; mt < 4; mt++) {
            unsigned ah[4];
            ldsm4(ah, s0 + aoff[mt]);
            #pragma unroll
            for (int j = 0; j < 2; j++) {
                mma_fp16(acc[mt][2*j],   ah, bh[j][0], bh[j][2]);
                mma_fp16(acc[mt][2*j+1], ah, bh[j][1], bh[j][3]);
            }
        }
        __syncthreads();
    }

    #pragma unroll
    for (int mt = 0; mt < 4; mt++) {
        #pragma unroll
        for (int nt = 0; nt < 4; nt++) {
            int rr = m0 + wm + mt * 16 + (lane >> 2);
            int cc = n0 + wn + nt * 8 + (lane & 3) * 2;
            if (cc < Nn) {
                float bv0 = bias ? bias[cc] : 0.f;
                float bv1 = bias ? bias[cc + 1] : 0.f;
                C[(long)rr * ldc + cc]           = acc[mt][nt][0] + bv0;
                C[(long)rr * ldc + cc + 1]       = acc[mt][nt][1] + bv1;
                C[(long)(rr + 8) * ldc + cc]     = acc[mt][nt][2] + bv0;
                C[(long)(rr + 8) * ldc + cc + 1] = acc[mt][nt][3] + bv1;
            }
        }
    }
}

__global__ void __launch_bounds__(256, 2) gemm1_k() {
    gemm_hmma(g_A, NFC, g_W, NFC,
              g_c1p + (long)blockIdx.z * (BSZ * DW), DW, DW,
              blockIdx.y * 128, blockIdx.x * 128,
              (long)blockIdx.z * CH1, NK1, nullptr);
}

__global__ void __launch_bounds__(256, 2) gemm2_k(
    const float* __restrict__ biasb, float* __restrict__ out) {
    gemm_hmma(g_z, KP2, g_n, KP2,
              out, NENT, NENT,
              blockIdx.y * 128, blockIdx.x * 128, 0, NK2, biasb);
}

// ---------------- kernel 6: split-K reduce (fc bias cancels in BN1d) ----------
__global__ void __launch_bounds__(256) reduce_c1() {
    int idx = blockIdx.x * 256 + threadIdx.x;
    float s = 0.f;
    #pragma unroll
    for (int z = 0; z < SK1; z++) s += g_c1p[z * (BSZ * DW) + idx];
    g_c1[idx] = s;
}

// ---------------- kernel 7: BN1d + ReLU -> fp16 (padded to KP2) ----------------
__global__ void __launch_bounds__(256) bn2_relu(
    const float* __restrict__ g2, const float* __restrict__ b2) {
    int d = blockIdx.x, t = threadIdx.x;
    if (d >= DW) {
        for (int b = t; b < BSZ; b += 256) g_z[b * KP2 + d] = __float2half(0.f);
        return;
    }
    float s = 0.f, q = 0.f;
    for (int b = t; b < BSZ; b += 256) {
        float v = g_c1[b * DW + d];
        s += v; q += v * v;
    }
    __shared__ float ss[256], sq[256];
    ss[t] = s; sq[t] = q; __syncthreads();
    for (int st = 128; st > 0; st >>= 1) {
        if (t < st) { ss[t] += ss[t + st]; sq[t] += sq[t + st]; }
        __syncthreads();
    }
    float mean = ss[0] / BSZ;
    float var  = sq[0] / BSZ - mean * mean;
    float a = g2[d] * rsqrtf(var + EPSB);
    float bb = b2[d] - mean * a;
    for (int b = t; b < BSZ; b += 256) {
        float v = fmaxf(fmaf(a, g_c1[b * DW + d], bb), 0.f);
        g_z[b * KP2 + d] = __float2half(v);
    }
}

// ---------------- launch ----------------
extern "C" void kernel_launch(void* const* d_in, const int* in_sizes, int n_in,
                              void* d_out, int out_size) {
    const float* n_feats = (const float*)d_in[0];
    const float* r_feats = (const float*)d_in[1];
    const float* filt1   = (const float*)d_in[2];
    const float* filt2   = (const float*)d_in[3];
    const float* filt3   = (const float*)d_in[4];
    const float* bn0_g   = (const float*)d_in[5];
    const float* bn0_b   = (const float*)d_in[6];
    const float* bn1_g   = (const float*)d_in[7];
    const float* bn1_b   = (const float*)d_in[8];
    const float* bn2c_g  = (const float*)d_in[9];
    const float* bn2c_b  = (const float*)d_in[10];
    const float* bn3c_g  = (const float*)d_in[11];
    const float* bn3c_b  = (const float*)d_in[12];
    const float* se1_w1  = (const float*)d_in[13];
    const float* se1_w2  = (const float*)d_in[14];
    const float* se2_w1  = (const float*)d_in[15];
    const float* se2_w2  = (const float*)d_in[16];
    const float* se3_w1  = (const float*)d_in[17];
    const float* se3_w2  = (const float*)d_in[18];
    const float* att_w1  = (const float*)d_in[19];
    const float* att_w2  = (const float*)d_in[20];
    const float* fc_w    = (const float*)d_in[21];
    const float* bn2_g   = (const float*)d_in[23];
    const float* bn2_b   = (const float*)d_in[24];
    const float* bias_b  = (const float*)d_in[25];
    const int*   sub     = (const int*)d_in[26];
    const int*   rel     = (const int*)d_in[27];

    const int ysmem = OC * HW * 2;   // 76800
    cudaFuncSetAttribute(conv3_fused,
                         cudaFuncAttributeMaxDynamicSharedMemorySize, ysmem);

    cudaStream_t s2;
    cudaStreamCreateWithFlags(&s2, cudaStreamNonBlocking);
    cudaEvent_t e1, e2;
    cudaEventCreateWithFlags(&e1, cudaEventDisableTiming);
    cudaEventCreateWithFlags(&e2, cudaEventDisableTiming);

    zero_stats<<<1, 3 * OC>>>();
    cudaEventRecord(e1, 0);
    cudaStreamWaitEvent(s2, e1, 0);
    convWN<<<WBLK + NBLK, 256, 0, s2>>>(fc_w, n_feats);

    gather_bn0<<<BSZ, 128>>>(n_feats, r_feats, sub, rel);
    conv3_stats<<<dim3(BSZ, 3), 384>>>(filt1, filt2, filt3, rel, bn0_g, bn0_b);
    bnaff<<<1, 3 * OC>>>(bn1_g, bn1_b, bn2c_g, bn2c_b, bn3c_g, bn3c_b);
    gates<<<BSZ, 128>>>(se1_w1, se1_w2, se2_w1, se2_w2, se3_w1, se3_w2,
                        att_w1, att_w2);
    conv3_fused<<<dim3(BSZ, 3), 384, ysmem>>>(filt1, filt2, filt3, rel,
                                              bn0_g, bn0_b);

    cudaEventRecord(e2, s2);
    cudaStreamWaitEvent(0, e2, 0);

    gemm1_k<<<dim3(2, BSZ / 128, SK1), 256>>>();
    reduce_c1<<<800, 256>>>();
    bn2_relu<<<KP2, 256>>>(bn2_g, bn2_b);
    gemm2_k<<<dim3((NENT + 127) / 128, BSZ / 128), 256>>>(bias_b, (float*)d_out);
}

// round 17
// speedup vs baseline: 1.7146x; 1.0452x over previous
#include <cuda_runtime.h>
#include <cuda_bf16.h>
#include <cuda_fp16.h>
#include <stdint.h>
#include <math.h>

// ---------------- problem constants ----------------
#define BSZ   1024
#define OC    96
#define DW    200          // d_embd
#define HW    400          // 20*20
#define NENT  40000
#define NFC   115200       // 3*96*400
#define EPSB  1e-5f
#define SK1   18
#define CH1   (NFC / SK1)  // 6400
#define NK1   (CH1 / 16)   // 400 k-steps of 16
#define KP2   208          // gemm2 K padded to mult of 16
#define NK2   (KP2 / 16)   // 13
#define WBLK  22500
#define NBLK  32500
#define XP    24           // padded image dim (2-halo)

// ---------------- device scratch ----------------
__device__ float g_x[BSZ * HW];
__device__ float g_bn0[2];
__device__ float g_bsum[3 * BSZ * OC];
__device__ float g_chsum[3 * OC];
__device__ float g_chsq[3 * OC];
__device__ float g_alpha[3 * OC];
__device__ float g_beta[3 * OC];
__device__ float g_scale[3 * BSZ * OC];
__device__ __align__(128) __half g_A [(long)BSZ * NFC];
__device__ __align__(128) __half g_W [(long)DW * NFC];
__device__ float g_c1p[SK1 * BSZ * DW];
__device__ float g_c1[BSZ * DW];
__device__ __align__(128) __half g_z [BSZ * KP2];
__device__ __align__(128) __half g_n [(long)NENT * KP2];

// ---------------- PTX helpers ----------------
__device__ __forceinline__ void ldsm4(unsigned r[4], unsigned addr) {
    asm volatile("ldmatrix.sync.aligned.m8n8.x4.shared.b16 {%0,%1,%2,%3}, [%4];"
        : "=r"(r[0]), "=r"(r[1]), "=r"(r[2]), "=r"(r[3]) : "r"(addr));
}
__device__ __forceinline__ void mma_fp16(float* c, const unsigned* a,
                                         unsigned b0, unsigned b1) {
    asm volatile(
        "mma.sync.aligned.m16n8k16.row.col.f32.f16.f16.f32 "
        "{%0,%1,%2,%3}, {%4,%5,%6,%7}, {%8,%9}, {%0,%1,%2,%3};"
        : "+f"(c[0]), "+f"(c[1]), "+f"(c[2]), "+f"(c[3])
        : "r"(a[0]), "r"(a[1]), "r"(a[2]), "r"(a[3]), "r"(b0), "r"(b1));
}
__device__ __forceinline__ void cpa16(unsigned s, const void* g) {
    asm volatile("cp.async.ca.shared.global [%0], [%1], 16;" :: "r"(s), "l"(g));
}
__device__ __forceinline__ void cpa16z(unsigned s, const void* g, int srcsz) {
    asm volatile("cp.async.ca.shared.global [%0], [%1], 16, %2;"
                 :: "r"(s), "l"(g), "r"(srcsz));
}

// ---------------- kernel 0: zero atomics ----------------
__global__ void zero_stats() {
    int t = threadIdx.x;
    if (t < 2) g_bn0[t] = 0.f;
    if (t < 3 * OC) { g_chsum[t] = 0.f; g_chsq[t] = 0.f; }
}

// ---------------- merged convert kernel (side stream) ----------------
__global__ void __launch_bounds__(256) convWN(const float* __restrict__ w,
                                             const float* __restrict__ nf) {
    long bid = blockIdx.x;
    if (bid < WBLK) {
        long i4 = bid * 256 + threadIdx.x;
        float4 v = ((const float4*)w)[i4];
        __half2 hh0, hh1;
        hh0.x = __float2half(v.x); hh0.y = __float2half(v.y);
        hh1.x = __float2half(v.z); hh1.y = __float2half(v.w);
        ((__half2*)g_W)[i4 * 2]     = hh0;
        ((__half2*)g_W)[i4 * 2 + 1] = hh1;
    } else {
        long t = (bid - WBLK) * 256 + threadIdx.x;
        int e = (int)(t / KP2), j = (int)(t - (long)e * KP2);
        float v = (j < DW) ? nf[(long)e * DW + j] : 0.f;
        g_n[t] = __float2half(v);
    }
}

// ---------------- kernel 1: gather + chequer + BN0 stats ----------------
__global__ void __launch_bounds__(128) gather_bn0(
    const float* __restrict__ n_feats, const float* __restrict__ r_feats,
    const int* __restrict__ sub, const int* __restrict__ rel)
{
    int b = blockIdx.x, t = threadIdx.x;
    int sb = sub[b], rb = rel[b];
    float s = 0.f, q = 0.f;
    for (int i = t; i < HW; i += 128) {
        float v = (i & 1) ? r_feats[rb * DW + (i >> 1)]
                          : n_feats[sb * DW + (i >> 1)];
        g_x[b * HW + i] = v;
        s += v; q += v * v;
    }
    __shared__ float ss[128], sq[128];
    ss[t] = s; sq[t] = q; __syncthreads();
    for (int st = 64; st > 0; st >>= 1) {
        if (t < st) { ss[t] += ss[t + st]; sq[t] += sq[t + st]; }
        __syncthreads();
    }
    if (t == 0) { atomicAdd(&g_bn0[0], ss[0]); atomicAdd(&g_bn0[1], sq[0]); }
}

// ---------------- padded-image loader ----------------
__device__ __forceinline__ void load_padded(float* xs, int b, float a0, float b0,
                                            int t, int nthr) {
    for (int i = t; i < XP * XP; i += nthr) xs[i] = 0.f;
    __syncthreads();
    for (int i = t; i < HW; i += nthr) {
        int h = i / 20, w = i - h * 20;
        xs[(h + 2) * XP + (w + 2)] = g_x[b * HW + i] * a0 + b0;
    }
    __syncthreads();
}

#define X(h_, w_) xs[((h_) + 2) * XP + ((w_) + 2)]

// ---------------- kernel 2a: conv stats (sliding windows) ----------------
__global__ void __launch_bounds__(384) conv3_stats(
    const float* __restrict__ f1, const float* __restrict__ f2,
    const float* __restrict__ f3, const int* __restrict__ rel,
    const float* __restrict__ bn0g, const float* __restrict__ bn0b)
{
    __shared__ float xs[XP * XP];
    __shared__ float fs[OC * 9];
    int b = blockIdx.x, brch = blockIdx.y, t = threadIdx.x;

    float N0 = (float)BSZ * HW;
    float mean = g_bn0[0] / N0;
    float var  = g_bn0[1] / N0 - mean * mean;
    float a0 = bn0g[0] * rsqrtf(var + EPSB);
    float b0 = bn0b[0] - mean * a0;

    int rb = rel[b];
    int flen = (brch == 1) ? OC * 9 : OC * 5;
    int fstr = (brch == 1) ? 9 : 5;
    const float* fp = (brch == 0 ? f1 : (brch == 1 ? f2 : f3)) + (long)rb * flen;
    for (int i = t; i < flen; i += 384) fs[i] = fp[i];
    load_padded(xs, b, a0, b0, t, 384);

    int oc = t >> 2, q = t & 3;
    int h0 = q * 5;
    const float* fo = &fs[oc * fstr];
    float lsum = 0.f, lsq = 0.f;

    if (brch == 0) {
        float k0 = fo[0], k1 = fo[1], k2 = fo[2], k3 = fo[3], k4 = fo[4];
        #pragma unroll
        for (int hh = 0; hh < 5; hh++) {
            int h = h0 + hh;
            float xm2 = X(h, -2), xm1 = X(h, -1), x0 = X(h, 0), xp1 = X(h, 1);
            #pragma unroll 5
            for (int w = 0; w < 20; w++) {
                float xp2 = X(h, w + 2);
                float acc = xm2 * k0 + xm1 * k1 + x0 * k2 + xp1 * k3 + xp2 * k4;
                lsum += acc; lsq += acc * acc;
                xm2 = xm1; xm1 = x0; x0 = xp1; xp1 = xp2;
            }
        }
    } else if (brch == 1) {
        float k0=fo[0],k1=fo[1],k2=fo[2],k3=fo[3],k4=fo[4],k5=fo[5],k6=fo[6],k7=fo[7],k8=fo[8];
        #pragma unroll
        for (int hh = 0; hh < 5; hh++) {
            int h = h0 + hh;
            float u0 = X(h-1,-1), u1 = X(h-1,0);
            float c0 = X(h,-1),   c1 = X(h,0);
            float d0 = X(h+1,-1), d1 = X(h+1,0);
            #pragma unroll 5
            for (int w = 0; w < 20; w++) {
                float u2 = X(h-1, w+1), c2 = X(h, w+1), d2 = X(h+1, w+1);
                float acc = u0*k0 + u1*k1 + u2*k2
                          + c0*k3 + c1*k4 + c2*k5
                          + d0*k6 + d1*k7 + d2*k8;
                lsum += acc; lsq += acc * acc;
                u0=u1; u1=u2; c0=c1; c1=c2; d0=d1; d1=d2;
            }
        }
    } else {
        float k0 = fo[0], k1 = fo[1], k2 = fo[2], k3 = fo[3], k4 = fo[4];
        #pragma unroll 4
        for (int w = 0; w < 20; w++) {
            float r0 = X(h0-2,w), r1 = X(h0-1,w), r2 = X(h0,w), r3 = X(h0+1,w);
            #pragma unroll
            for (int hh = 0; hh < 5; hh++) {
                float r4 = X(h0+hh+2, w);
                float acc = r0*k0 + r1*k1 + r2*k2 + r3*k3 + r4*k4;
                lsum += acc; lsq += acc * acc;
                r0 = r1; r1 = r2; r2 = r3; r3 = r4;
            }
        }
    }

    lsum += __shfl_down_sync(0xffffffffu, lsum, 2, 4);
    lsum += __shfl_down_sync(0xffffffffu, lsum, 1, 4);
    lsq  += __shfl_down_sync(0xffffffffu, lsq, 2, 4);
    lsq  += __shfl_down_sync(0xffffffffu, lsq, 1, 4);
    if (q == 0) {
        g_bsum[(brch * BSZ + b) * OC + oc] = lsum;
        atomicAdd(&g_chsum[brch * OC + oc], lsum);
        atomicAdd(&g_chsq[brch * OC + oc], lsq);
    }
}

// ---------------- kernel 3: BN affine ----------------
__global__ void bnaff(
    const float* __restrict__ g1, const float* __restrict__ b1,
    const float* __restrict__ g2, const float* __restrict__ b2,
    const float* __restrict__ g3, const float* __restrict__ b3)
{
    int i = threadIdx.x;
    if (i < 3 * OC) {
        int brch = i / OC, c = i - brch * OC;
        float N = (float)BSZ * HW;
        float mean = g_chsum[i] / N;
        float var  = g_chsq[i] / N - mean * mean;
        const float* g = brch == 0 ? g1 : (brch == 1 ? g2 : g3);
        const float* bb = brch == 0 ? b1 : (brch == 1 ? b2 : b3);
        float a = g[c] * rsqrtf(var + EPSB);
        g_alpha[i] = a;
        g_beta[i]  = bb[c] - mean * a;
    }
}

// ---------------- reductions ----------------
__device__ __forceinline__ float redsum128(float v, float* sm) {
    int t = threadIdx.x;
    sm[t] = v; __syncthreads();
    for (int s = 64; s > 0; s >>= 1) {
        if (t < s) sm[t] += sm[t + s];
        __syncthreads();
    }
    float r = sm[0]; __syncthreads();
    return r;
}
__device__ __forceinline__ float redmax128(float v, float* sm) {
    int t = threadIdx.x;
    sm[t] = v; __syncthreads();
    for (int s = 64; s > 0; s >>= 1) {
        if (t < s) sm[t] = fmaxf(sm[t], sm[t + s]);
        __syncthreads();
    }
    float r = sm[0]; __syncthreads();
    return r;
}

// ---------------- kernel 4: SE + ATT gates ----------------
__global__ void __launch_bounds__(128) gates(
    const float* __restrict__ s1w1, const float* __restrict__ s1w2,
    const float* __restrict__ s2w1, const float* __restrict__ s2w2,
    const float* __restrict__ s3w1, const float* __restrict__ s3w2,
    const float* __restrict__ aw1, const float* __restrict__ aw2)
{
    __shared__ float sm[128];
    int b = blockIdx.x, t = threadIdx.x;
    bool act = t < OC;
    int oc = act ? t : 0;

    const float* w1s[3] = {s1w1, s2w1, s3w1};
    const float* w2s[3] = {s1w2, s2w2, s3w2};

    float pool[3], seg[3];
    #pragma unroll
    for (int br = 0; br < 3; br++) {
        float p = fmaf(g_alpha[br * OC + oc],
                       g_bsum[(br * BSZ + b) * OC + oc] * (1.f / HW),
                       g_beta[br * OC + oc]);
        pool[br] = act ? p : 0.f;
    }
    #pragma unroll
    for (int br = 0; br < 3; br++) {
        float h0 = redsum128(act ? pool[br] * w1s[br][oc] : 0.f, sm);
        float h1 = redsum128(act ? pool[br] * w1s[br][OC + oc] : 0.f, sm);
        h0 = fmaxf(h0, 0.f); h1 = fmaxf(h1, 0.f);
        float lg = h0 * w2s[br][oc * 2] + h1 * w2s[br][oc * 2 + 1];
        seg[br] = 1.f / (1.f + expf(-lg));
    }
    float attp = seg[0] * pool[0] + seg[1] * pool[1] + seg[2] * pool[2];
    float a0 = fmaxf(redsum128(act ? attp * aw1[oc] : 0.f, sm), 0.f);
    float a1 = fmaxf(redsum128(act ? attp * aw1[OC + oc] : 0.f, sm), 0.f);

    float l[3], mx = -1e30f;
    #pragma unroll
    for (int br = 0; br < 3; br++) {
        l[br] = act ? (a0 * aw2[(br * OC + oc) * 2] + a1 * aw2[(br * OC + oc) * 2 + 1])
                    : -1e30f;
        mx = fmaxf(mx, l[br]);
    }
    float gm = redmax128(mx, sm);
    float e[3], le = 0.f;
    #pragma unroll
    for (int br = 0; br < 3; br++) { e[br] = expf(l[br] - gm); le += e[br]; }
    float S = redsum128(le, sm);
    if (act) {
        #pragma unroll
        for (int br = 0; br < 3; br++)
            g_scale[(br * BSZ + b) * OC + oc] = seg[br] * e[br] / S;
    }
}

// ---------------- kernel 2b: conv + gate + relu -> smem stage -> coalesced A ---
__global__ void __launch_bounds__(384) conv3_fused(
    const float* __restrict__ f1, const float* __restrict__ f2,
    const float* __restrict__ f3, const int* __restrict__ rel,
    const float* __restrict__ bn0g, const float* __restrict__ bn0b)
{
    __shared__ float xs[XP * XP];
    __shared__ float fs[OC * 9];
    __shared__ float sA[OC], sBt[OC], sS[OC];
    extern __shared__ __half ybuf[];    // OC*HW halves = 76800 B
    int b = blockIdx.x, brch = blockIdx.y, t = threadIdx.x;

    float N0 = (float)BSZ * HW;
    float mean = g_bn0[0] / N0;
    float var  = g_bn0[1] / N0 - mean * mean;
    float a0 = bn0g[0] * rsqrtf(var + EPSB);
    float b0 = bn0b[0] - mean * a0;

    int rb = rel[b];
    int flen = (brch == 1) ? OC * 9 : OC * 5;
    int fstr = (brch == 1) ? 9 : 5;
    const float* fp = (brch == 0 ? f1 : (brch == 1 ? f2 : f3)) + (long)rb * flen;
    for (int i = t; i < flen; i += 384) fs[i] = fp[i];
    if (t < OC) {
        sA[t]  = g_alpha[brch * OC + t];
        sBt[t] = g_beta[brch * OC + t];
        sS[t]  = g_scale[(brch * BSZ + b) * OC + t];
    }
    load_padded(xs, b, a0, b0, t, 384);

    int oc = t >> 2, q = t & 3;
    int h0 = q * 5;
    const float* fo = &fs[oc * fstr];
    float ga = sA[oc], gb = sBt[oc], gs = sS[oc];
    __half* yrow = &ybuf[oc * HW];

    #define EMIT(acc_, h_, w_) do {                                    \
        float v_ = fmaxf(fmaf(ga, (acc_), gb) * gs, 0.f);              \
        yrow[(h_) * 20 + (w_)] = __float2half(v_);                     \
    } while (0)

    if (brch == 0) {
        float k0 = fo[0], k1 = fo[1], k2 = fo[2], k3 = fo[3], k4 = fo[4];
        #pragma unroll
        for (int hh = 0; hh < 5; hh++) {
            int h = h0 + hh;
            float xm2 = X(h, -2), xm1 = X(h, -1), x0 = X(h, 0), xp1 = X(h, 1);
            #pragma unroll 5
            for (int w = 0; w < 20; w++) {
                float xp2 = X(h, w + 2);
                float acc = xm2 * k0 + xm1 * k1 + x0 * k2 + xp1 * k3 + xp2 * k4;
                EMIT(acc, h, w);
                xm2 = xm1; xm1 = x0; x0 = xp1; xp1 = xp2;
            }
        }
    } else if (brch == 1) {
        float k0=fo[0],k1=fo[1],k2=fo[2],k3=fo[3],k4=fo[4],k5=fo[5],k6=fo[6],k7=fo[7],k8=fo[8];
        #pragma unroll
        for (int hh = 0; hh < 5; hh++) {
            int h = h0 + hh;
            float u0 = X(h-1,-1), u1 = X(h-1,0);
            float c0 = X(h,-1),   c1 = X(h,0);
            float d0 = X(h+1,-1), d1 = X(h+1,0);
            #pragma unroll 5
            for (int w = 0; w < 20; w++) {
                float u2 = X(h-1, w+1), c2 = X(h, w+1), d2 = X(h+1, w+1);
                float acc = u0*k0 + u1*k1 + u2*k2
                          + c0*k3 + c1*k4 + c2*k5
                          + d0*k6 + d1*k7 + d2*k8;
                EMIT(acc, h, w);
                u0=u1; u1=u2; c0=c1; c1=c2; d0=d1; d1=d2;
            }
        }
    } else {
        float k0 = fo[0], k1 = fo[1], k2 = fo[2], k3 = fo[3], k4 = fo[4];
        #pragma unroll 4
        for (int w = 0; w < 20; w++) {
            float r0 = X(h0-2,w), r1 = X(h0-1,w), r2 = X(h0,w), r3 = X(h0+1,w);
            #pragma unroll
            for (int hh = 0; hh < 5; hh++) {
                float r4 = X(h0+hh+2, w);
                float acc = r0*k0 + r1*k1 + r2*k2 + r3*k3 + r4*k4;
                EMIT(acc, h0 + hh, w);
                r0 = r1; r1 = r2; r2 = r3; r3 = r4;
            }
        }
    }
    #undef EMIT
    __syncthreads();

    const uint4* src = (const uint4*)ybuf;
    uint4* dst = (uint4*)(g_A + (long)b * NFC + (long)brch * (OC * HW));
    for (int i = t; i < OC * HW / 8; i += 384) dst[i] = src[i];
}

// ---------------- HMMA fp16 GEMM: 128x128 tile, kstep16, 3 stages, occ-2 --------
__device__ __forceinline__ void gemm_hmma(
    const __half* __restrict__ A, long lda,
    const __half* __restrict__ B, long ldb,
    float* __restrict__ C, long ldc, int Nn,
    int m0, int n0, long k0, int nk, const float* __restrict__ bias)
{
    __shared__ __align__(16) char smem[24576];
    unsigned sb = (unsigned)__cvta_generic_to_shared(smem);
    int tid = threadIdx.x, lane = tid & 31, wid = tid >> 5;
    int wm = (wid >> 2) * 64, wn = (wid & 3) * 32;

    float acc[4][4][4];
    #pragma unroll
    for (int i = 0; i < 4; i++)
        #pragma unroll
        for (int j = 0; j < 4; j++)
            #pragma unroll
            for (int k = 0; k < 4; k++) acc[i][j][k] = 0.f;

    auto issue = [&](int stg_, int kb_) {
        unsigned s0_ = sb + (unsigned)stg_ * 8192u;
        long kk_ = k0 + (long)kb_ * 16;
        #pragma unroll
        for (int ii = 0; ii < 2; ii++) {
            int i_ = tid + ii * 256;
            int pl_ = i_ >> 8, r_ = (i_ >> 1) & 127, c_ = i_ & 1;
            unsigned sw_ = s0_ + (unsigned)pl_ * 4096u + (unsigned)r_ * 32u
                         + (unsigned)((c_ ^ ((r_ >> 2) & 1)) * 16);
            if (pl_ == 0) {
                cpa16(sw_, A + (long)(m0 + r_) * lda + kk_ + c_ * 8);
            } else {
                int ok_ = ((n0 + r_) < Nn) ? 16 : 0;
                cpa16z(sw_, B + (long)(n0 + r_) * ldb + kk_ + c_ * 8, ok_);
            }
        }
        asm volatile("cp.async.commit_group;" ::: "memory");
    };

    int cbit = lane >> 4;
    unsigned aoff[4], boff[2];
    #pragma unroll
    for (int mt = 0; mt < 4; mt++) {
        int r = wm + mt * 16 + (lane & 15);
        aoff[mt] = (unsigned)r * 32u + (unsigned)((cbit ^ ((r >> 2) & 1)) * 16);
    }
    #pragma unroll
    for (int j = 0; j < 2; j++) {
        int r = wn + j * 16 + (lane & 15);
        boff[j] = 4096u + (unsigned)r * 32u
                + (unsigned)((cbit ^ ((r >> 2) & 1)) * 16);
    }

    issue(0, 0);
    issue(1, 1);

    for (int kb = 0; kb < nk; kb++) {
        int st = kb % 3;
        if (kb + 1 < nk)
            asm volatile("cp.async.wait_group 1;" ::: "memory");
        else
            asm volatile("cp.async.wait_group 0;" ::: "memory");
        __syncthreads();
        if (kb + 2 < nk) issue((kb + 2) % 3, kb + 2);

        unsigned s0 = sb + (unsigned)st * 8192u;
        unsigned bh[2][4];
        #pragma unroll
        for (int j = 0; j < 2; j++) ldsm4(bh[j], s0 + boff[j]);
        #pragma unroll
        for (int mt = 0; mt < 4; mt++) {
            unsigned ah[4];
            ldsm4(ah, s0 + aoff[mt]);
            #pragma unroll
            for (int j = 0; j < 2; j++) {
                mma_fp16(acc[mt][2*j],   ah, bh[j][0], bh[j][2]);
                mma_fp16(acc[mt][2*j+1], ah, bh[j][1], bh[j][3]);
            }
        }
        __syncthreads();
    }

    #pragma unroll
    for (int mt = 0; mt < 4; mt++) {
        #pragma unroll
        for (int nt = 0; nt < 4; nt++) {
            int rr = m0 + wm + mt * 16 + (lane >> 2);
            int cc = n0 + wn + nt * 8 + (lane & 3) * 2;
            if (cc < Nn) {   // cc even, Nn even -> pair valid; ldc even -> aligned
                float bv0 = bias ? bias[cc] : 0.f;
                float bv1 = bias ? bias[cc + 1] : 0.f;
                float2 v0 = make_float2(acc[mt][nt][0] + bv0, acc[mt][nt][1] + bv1);
                float2 v1 = make_float2(acc[mt][nt][2] + bv0, acc[mt][nt][3] + bv1);
                *(float2*)&C[(long)rr * ldc + cc]       = v0;
                *(float2*)&C[(long)(rr + 8) * ldc + cc] = v1;
            }
        }
    }
}

__global__ void __launch_bounds__(256, 2) gemm1_k() {
    gemm_hmma(g_A, NFC, g_W, NFC,
              g_c1p + (long)blockIdx.z * (BSZ * DW), DW, DW,
              blockIdx.y * 128, blockIdx.x * 128,
              (long)blockIdx.z * CH1, NK1, nullptr);
}

__global__ void __launch_bounds__(256, 2) gemm2_k(
    const float* __restrict__ biasb, float* __restrict__ out) {
    gemm_hmma(g_z, KP2, g_n, KP2,
              out, NENT, NENT,
              blockIdx.y * 128, blockIdx.x * 128, 0, NK2, biasb);
}

// ---------------- kernel 6: split-K reduce ----------------
__global__ void __launch_bounds__(256) reduce_c1() {
    int idx = blockIdx.x * 256 + threadIdx.x;
    float s = 0.f;
    #pragma unroll
    for (int z = 0; z < SK1; z++) s += g_c1p[z * (BSZ * DW) + idx];
    g_c1[idx] = s;
}

// ---------------- kernel 7: BN1d + ReLU -> fp16 ----------------
__global__ void __launch_bounds__(256) bn2_relu(
    const float* __restrict__ g2, const float* __restrict__ b2) {
    int d = blockIdx.x, t = threadIdx.x;
    if (d >= DW) {
        for (int b = t; b < BSZ; b += 256) g_z[b * KP2 + d] = __float2half(0.f);
        return;
    }
    float s = 0.f, q = 0.f;
    for (int b = t; b < BSZ; b += 256) {
        float v = g_c1[b * DW + d];
        s += v; q += v * v;
    }
    __shared__ float ss[256], sq[256];
    ss[t] = s; sq[t] = q; __syncthreads();
    for (int st = 128; st > 0; st >>= 1) {
        if (t < st) { ss[t] += ss[t + st]; sq[t] += sq[t + st]; }
        __syncthreads();
    }
    float mean = ss[0] / BSZ;
    float var  = sq[0] / BSZ - mean * mean;
    float a = g2[d] * rsqrtf(var + EPSB);
    float bb = b2[d] - mean * a;
    for (int b = t; b < BSZ; b += 256) {
        float v = fmaxf(fmaf(a, g_c1[b * DW + d], bb), 0.f);
        g_z[b * KP2 + d] = __float2half(v);
    }
}

// ---------------- launch ----------------
extern "C" void kernel_launch(void* const* d_in, const int* in_sizes, int n_in,
                              void* d_out, int out_size) {
    const float* n_feats = (const float*)d_in[0];
    const float* r_feats = (const float*)d_in[1];
    const float* filt1   = (const float*)d_in[2];
    const float* filt2   = (const float*)d_in[3];
    const float* filt3   = (const float*)d_in[4];
    const float* bn0_g   = (const float*)d_in[5];
    const float* bn0_b   = (const float*)d_in[6];
    const float* bn1_g   = (const float*)d_in[7];
    const float* bn1_b   = (const float*)d_in[8];
    const float* bn2c_g  = (const float*)d_in[9];
    const float* bn2c_b  = (const float*)d_in[10];
    const float* bn3c_g  = (const float*)d_in[11];
    const float* bn3c_b  = (const float*)d_in[12];
    const float* se1_w1  = (const float*)d_in[13];
    const float* se1_w2  = (const float*)d_in[14];
    const float* se2_w1  = (const float*)d_in[15];
    const float* se2_w2  = (const float*)d_in[16];
    const float* se3_w1  = (const float*)d_in[17];
    const float* se3_w2  = (const float*)d_in[18];
    const float* att_w1  = (const float*)d_in[19];
    const float* att_w2  = (const float*)d_in[20];
    const float* fc_w    = (const float*)d_in[21];
    const float* bn2_g   = (const float*)d_in[23];
    const float* bn2_b   = (const float*)d_in[24];
    const float* bias_b  = (const float*)d_in[25];
    const int*   sub     = (const int*)d_in[26];
    const int*   rel     = (const int*)d_in[27];

    const int ysmem = OC * HW * 2;   // 76800
    cudaFuncSetAttribute(conv3_fused,
                         cudaFuncAttributeMaxDynamicSharedMemorySize, ysmem);

    cudaStream_t s2;
    cudaStreamCreateWithFlags(&s2, cudaStreamNonBlocking);
    cudaEvent_t e1, e2;
    cudaEventCreateWithFlags(&e1, cudaEventDisableTiming);
    cudaEventCreateWithFlags(&e2, cudaEventDisableTiming);

    zero_stats<<<1, 3 * OC>>>();
    cudaEventRecord(e1, 0);
    cudaStreamWaitEvent(s2, e1, 0);
    convWN<<<WBLK + NBLK, 256, 0, s2>>>(fc_w, n_feats);

    gather_bn0<<<BSZ, 128>>>(n_feats, r_feats, sub, rel);
    conv3_stats<<<dim3(BSZ, 3), 384>>>(filt1, filt2, filt3, rel, bn0_g, bn0_b);
    bnaff<<<1, 3 * OC>>>(bn1_g, bn1_b, bn2c_g, bn2c_b, bn3c_g, bn3c_b);
    gates<<<BSZ, 128>>>(se1_w1, se1_w2, se2_w1, se2_w2, se3_w1, se3_w2,
                        att_w1, att_w2);
    conv3_fused<<<dim3(BSZ, 3), 384, ysmem>>>(filt1, filt2, filt3, rel,
                                              bn0_g, bn0_b);

    cudaEventRecord(e2, s2);
    cudaStreamWaitEvent(0, e2, 0);

    gemm1_k<<<dim3(2, BSZ / 128, SK1), 256>>>();
    reduce_c1<<<800, 256>>>();
    bn2_relu<<<KP2, 256>>>(bn2_g, bn2_b);
    gemm2_k<<<dim3((NENT + 127) / 128, BSZ / 128), 256>>>(bias_b, (float*)d_out);
}